// round 3
// baseline (speedup 1.0000x reference)
#include <cuda_runtime.h>

#define TOT 37440

__device__ float g_in36[36 * TOT];
__device__ float g_bufA[64 * TOT];
__device__ float g_bufB[64 * TOT];
__device__ float g_mean[256];   // [4 levels][64 ch]
__device__ float g_rstd[256];

typedef unsigned long long u64;

__device__ __forceinline__ u64 pack2(float lo, float hi) {
    u64 d;
    asm("mov.b64 %0, {%1, %2};" : "=l"(d) : "f"(lo), "f"(hi));
    return d;
}
__device__ __forceinline__ void unpack2(u64 v, float& lo, float& hi) {
    asm("mov.b64 {%0, %1}, %2;" : "=f"(lo), "=f"(hi) : "l"(v));
}
__device__ __forceinline__ u64 ffma2(u64 a, u64 b, u64 c) {
    u64 d;
    asm("fma.rn.f32x2 %0, %1, %2, %3;" : "=l"(d) : "l"(a), "l"(b), "l"(c));
    return d;
}

// ---------------------------------------------------------------------------
__global__ void pack_kernel(const float* __restrict__ p0, const float* __restrict__ p1,
                            const float* __restrict__ p2, const float* __restrict__ p3,
                            float* __restrict__ out) {
    int c = blockIdx.y;
    int pos = blockIdx.x * 256 + threadIdx.x;
    if (pos >= TOT) return;
    const float* p; int v, voxn;
    if (pos < 32768)      { p = p0; v = pos;         voxn = 32768; }
    else if (pos < 36864) { p = p1; v = pos - 32768; voxn = 4096;  }
    else if (pos < 37376) { p = p2; v = pos - 36864; voxn = 512;   }
    else                  { p = p3; v = pos - 37376; voxn = 64;    }
    out[c * TOT + pos] = p[c * voxn + v];
}

// ---------------------------------------------------------------------------
__global__ void stats_kernel(const float* __restrict__ buf,
                             float* __restrict__ mean, float* __restrict__ rstd) {
    __shared__ float ss[256], sq[256];
    int L = blockIdx.x >> 6, c = blockIdx.x & 63;
    const int voxs[4] = {32768, 4096, 512, 64};
    const int offs[4] = {0, 32768, 36864, 37376};
    int N = voxs[L];
    const float* p = buf + c * TOT + offs[L];
    float s = 0.f, q = 0.f;
    for (int i = threadIdx.x; i < N; i += 256) {
        float x = p[i];
        s += x;
        q = fmaf(x, x, q);
    }
    ss[threadIdx.x] = s; sq[threadIdx.x] = q;
    __syncthreads();
    for (int st = 128; st > 0; st >>= 1) {
        if (threadIdx.x < st) {
            ss[threadIdx.x] += ss[threadIdx.x + st];
            sq[threadIdx.x] += sq[threadIdx.x + st];
        }
        __syncthreads();
    }
    if (threadIdx.x == 0) {
        float m = ss[0] / (float)N;
        float v = sq[0] / (float)N - m * m;
        mean[blockIdx.x] = m;
        rstd[blockIdx.x] = rsqrtf(fmaxf(v, 0.f) + 1e-5f);
    }
}

// ---------------------------------------------------------------------------
template <int LEV> struct Geo;
template <> struct Geo<0> { enum { S = 32, OFF = 0,     ZT = 4,  YT = 10, XT = 34, XP = 35 }; };
template <> struct Geo<1> { enum { S = 16, OFF = 32768, ZT = 6,  YT = 10, XT = 18, XP = 19 }; };
template <> struct Geo<2> { enum { S = 8,  OFF = 36864, ZT = 10, YT = 10, XT = 10, XP = 11 }; };
template <> struct Geo<3> { enum { S = 4,  OFF = 37376, ZT = 6,  YT = 6,  XT = 6,  XP = 7  }; };

// ---------------------------------------------------------------------------
// Per-level conv body. 128 threads; active thread computes 4 consecutive W
// voxels (as 2x f32x2 accumulators) x OCW output channels. Double-buffered
// smem; weights pre-duplicated (w,w) for packed FMA. One barrier per ic.
// ---------------------------------------------------------------------------
template <int LEV, int OCW, bool FINAL, bool NORM>
__device__ __forceinline__ void conv_body(
    int sp, int ocg,
    const float* __restrict__ in, const float* __restrict__ wgt,
    const float* __restrict__ bias, float* __restrict__ out,
    const float* __restrict__ mean, const float* __restrict__ rstd,
    float alpha, int CIN, int COUT, int head_base,
    float* __restrict__ in_s, u64* __restrict__ w_s) {

    typedef Geo<LEV> G;
    constexpr int S  = G::S,  OFF = G::OFF;
    constexpr int ZT = G::ZT, YT = G::YT, XT = G::XT, XP = G::XP;
    constexpr int TILE = ZT * YT * XP;
    constexpr int TOTE = ZT * YT * XT;
    constexpr int WSL  = OCW * 27;

    const int t = threadIdx.x;
    int tz, ty, tx, d0 = 0, h0 = 0;
    bool active = true;
    if (LEV == 0) { tx = t & 7; ty = (t >> 3) & 7; tz = t >> 6;
                    d0 = (sp >> 2) * 2; h0 = (sp & 3) * 8; }
    else if (LEV == 1) { tx = t & 3; ty = (t >> 2) & 7; tz = t >> 5;
                    d0 = (sp >> 1) * 4; h0 = (sp & 1) * 8; }
    else if (LEV == 2) { tx = t & 1; ty = (t >> 1) & 7; tz = t >> 4; }
    else { tx = 0; ty = t & 3; tz = (t >> 2) & 3; active = (t < 16); }

    u64 accA[OCW], accB[OCW];
#pragma unroll
    for (int j = 0; j < OCW; ++j) { accA[j] = 0ull; accB[j] = 0ull; }

    auto load_tile = [&](int b, int ic) {
        float m = 0.f, r = 0.f;
        if (NORM) { m = mean[LEV * 64 + ic]; r = rstd[LEV * 64 + ic]; }
        const float* src = in + ic * TOT + OFF;
        float* dst = in_s + b * TILE;
#pragma unroll
        for (int i = 0; i < (TOTE + 127) / 128; ++i) {
            int idx = i * 128 + t;
            if ((TOTE % 128 == 0) || idx < TOTE) {
                int z = idx / (YT * XT), rem = idx - z * (YT * XT);
                int y = rem / XT, x = rem - y * XT;
                int gz = d0 - 1 + z, gy = h0 - 1 + y, gx = x - 1;
                float v = 0.f;
                if ((unsigned)gz < (unsigned)S && (unsigned)gy < (unsigned)S &&
                    (unsigned)gx < (unsigned)S) {
                    v = src[(gz * S + gy) * S + gx];
                    if (NORM) {
                        v = (v - m) * r;
                        v = v >= 0.f ? v : alpha * v;
                    }
                }
                dst[(z * YT + y) * XP + x] = v;
            }
        }
    };
    auto load_w = [&](int b, int ic) {
#pragma unroll
        for (int i = t; i < WSL; i += 128) {
            int j = i / 27, k = i - j * 27;
            int oc = ocg * OCW + j;
            float w = (oc < COUT) ? wgt[(oc * CIN + ic) * 27 + k] : 0.f;
            w_s[b * WSL + i] = pack2(w, w);
        }
    };

    load_tile(0, 0);
    load_w(0, 0);

    for (int ic = 0; ic < CIN; ++ic) {
        __syncthreads();
        int cur = ic & 1, nb = cur ^ 1;
        if (ic + 1 < CIN) { load_tile(nb, ic + 1); load_w(nb, ic + 1); }

        if (active) {
            const float* buf = in_s + cur * TILE;
            const u64* wb = w_s + cur * WSL;
#pragma unroll
            for (int kz = 0; kz < 3; ++kz) {
#pragma unroll
                for (int ky = 0; ky < 3; ++ky) {
                    const float* ip = &buf[((tz + kz) * YT + (ty + ky)) * XP + (tx << 2)];
                    float x0 = ip[0], x1 = ip[1], x2 = ip[2];
                    float x3 = ip[3], x4 = ip[4], x5 = ip[5];
                    u64 p0 = pack2(x0, x1);
                    u64 p1 = pack2(x1, x2);
                    u64 p2 = pack2(x2, x3);
                    u64 p3 = pack2(x3, x4);
                    u64 p4 = pack2(x4, x5);
                    const u64* wr = wb + (kz * 3 + ky) * 3;
#pragma unroll
                    for (int j = 0; j < OCW; ++j) {
                        u64 w0 = wr[j * 27 + 0];
                        u64 w1 = wr[j * 27 + 1];
                        u64 w2 = wr[j * 27 + 2];
                        accA[j] = ffma2(p0, w0, accA[j]);
                        accB[j] = ffma2(p2, w0, accB[j]);
                        accA[j] = ffma2(p1, w1, accA[j]);
                        accB[j] = ffma2(p3, w1, accB[j]);
                        accA[j] = ffma2(p2, w2, accA[j]);
                        accB[j] = ffma2(p4, w2, accB[j]);
                    }
                }
            }
        }
    }

    if (!active) return;
    int d = d0 + tz, h = h0 + ty, w0i = tx << 2;
    int vidx = (d * S + h) * S + w0i;
#pragma unroll
    for (int j = 0; j < OCW; ++j) {
        int oc = ocg * OCW + j;
        if (oc >= COUT) break;
        float b = bias[oc];
        float a0, a1, a2, a3;
        unpack2(accA[j], a0, a1);
        unpack2(accB[j], a2, a3);
        if (FINAL) {
            int base = head_base + (OFF + vidx) * COUT + oc;
            out[base + 0 * COUT] = a0 + b;
            out[base + 1 * COUT] = a1 + b;
            out[base + 2 * COUT] = a2 + b;
            out[base + 3 * COUT] = a3 + b;
        } else {
            float* o = out + oc * TOT + OFF + vidx;
            o[0] = a0 + b;
            o[1] = a1 + b;
            o[2] = a2 + b;
            o[3] = a3 + b;
        }
    }
}

// ---------------------------------------------------------------------------
template <int OCW, bool FINAL, bool NORM>
__global__ void __launch_bounds__(128) conv_kernel(
    const float* __restrict__ in, const float* __restrict__ wgt,
    const float* __restrict__ bias, float* __restrict__ out,
    const float* __restrict__ mean, const float* __restrict__ rstd,
    const float* __restrict__ aP, int aidx,
    int CIN, int COUT, int head_base) {
    __shared__ float in_s[2 * 1400];
    __shared__ u64 w_s[2 * OCW * 27];

    int ocg = blockIdx.x / 74;
    int r = blockIdx.x - ocg * 74;
    float alpha = NORM ? __ldg(aP + aidx) : 0.f;

    if (r < 64)
        conv_body<0, OCW, FINAL, NORM>(r, ocg, in, wgt, bias, out, mean, rstd,
                                       alpha, CIN, COUT, head_base, in_s, w_s);
    else if (r < 72)
        conv_body<1, OCW, FINAL, NORM>(r - 64, ocg, in, wgt, bias, out, mean, rstd,
                                       alpha, CIN, COUT, head_base, in_s, w_s);
    else if (r == 72)
        conv_body<2, OCW, FINAL, NORM>(0, ocg, in, wgt, bias, out, mean, rstd,
                                       alpha, CIN, COUT, head_base, in_s, w_s);
    else
        conv_body<3, OCW, FINAL, NORM>(0, ocg, in, wgt, bias, out, mean, rstd,
                                       alpha, CIN, COUT, head_base, in_s, w_s);
}

// ---------------------------------------------------------------------------
extern "C" void kernel_launch(void* const* d_in, const int* in_sizes, int n_in,
                              void* d_out, int out_size) {
    (void)in_sizes; (void)n_in; (void)out_size;

    const float* p0 = (const float*)d_in[0];
    const float* p1 = (const float*)d_in[1];
    const float* p2 = (const float*)d_in[2];
    const float* p3 = (const float*)d_in[3];

    float *in36, *bufA, *bufB, *mean, *rstd;
    cudaGetSymbolAddress((void**)&in36, g_in36);
    cudaGetSymbolAddress((void**)&bufA, g_bufA);
    cudaGetSymbolAddress((void**)&bufB, g_bufB);
    cudaGetSymbolAddress((void**)&mean, g_mean);
    cudaGetSymbolAddress((void**)&rstd, g_rstd);

    float* out = (float*)d_out;

    pack_kernel<<<dim3(147, 36), 256>>>(p0, p1, p2, p3, in36);

    const int CLS_TOTAL = TOT * 18;

    for (int head = 0; head < 2; ++head) {
        int base = 4 + head * 7;
        const float* w1   = (const float*)d_in[base + 0];
        const float* b1   = (const float*)d_in[base + 1];
        const float* w234 = (const float*)d_in[base + 2];
        const float* b234 = (const float*)d_in[base + 3];
        const float* aP   = (const float*)d_in[base + 4];
        const float* wf   = (const float*)d_in[base + 5];
        const float* bf   = (const float*)d_in[base + 6];

        conv_kernel<8, false, false><<<8 * 74, 128>>>(
            in36, w1, b1, bufA, mean, rstd, aP, 0, 36, 64, 0);
        stats_kernel<<<256, 256>>>(bufA, mean, rstd);

        float* src = bufA; float* dst = bufB;
        for (int i = 0; i < 3; ++i) {
            conv_kernel<8, false, true><<<8 * 74, 128>>>(
                src, w234 + (size_t)i * 64 * 64 * 27, b234 + i * 64, dst,
                mean, rstd, aP, i, 64, 64, 0);
            stats_kernel<<<256, 256>>>(dst, mean, rstd);
            float* tmp = src; src = dst; dst = tmp;
        }

        if (head == 0) {
            conv_kernel<6, true, true><<<3 * 74, 128>>>(
                src, wf, bf, out, mean, rstd, aP, 3, 64, 18, 0);
        } else {
            conv_kernel<6, true, true><<<9 * 74, 128>>>(
                src, wf, bf, out, mean, rstd, aP, 3, 64, 54, CLS_TOTAL);
        }
    }
}

// round 4
// speedup vs baseline: 1.6483x; 1.6483x over previous
#include <cuda_runtime.h>

#define TOT 37440

__device__ float g_in36[36 * TOT];
__device__ float g_buf[2][2][64 * TOT];   // [head][pingpong]
__device__ float g_mean[512];             // [head][4 levels][64 ch]
__device__ float g_rstd[512];

// ---------------------------------------------------------------------------
__global__ void pack_kernel(const float* __restrict__ p0, const float* __restrict__ p1,
                            const float* __restrict__ p2, const float* __restrict__ p3,
                            float* __restrict__ out) {
    int c = blockIdx.y;
    int pos = blockIdx.x * 256 + threadIdx.x;
    if (pos >= TOT) return;
    const float* p; int v, voxn;
    if (pos < 32768)      { p = p0; v = pos;         voxn = 32768; }
    else if (pos < 36864) { p = p1; v = pos - 32768; voxn = 4096;  }
    else if (pos < 37376) { p = p2; v = pos - 36864; voxn = 512;   }
    else                  { p = p3; v = pos - 37376; voxn = 64;    }
    out[c * TOT + pos] = p[c * voxn + v];
}

// ---------------------------------------------------------------------------
// Per-(head,level,channel) mean/rstd. 512 blocks, deterministic tree-reduce.
// ---------------------------------------------------------------------------
__global__ void stats2_kernel(const float* __restrict__ b0, const float* __restrict__ b1,
                              float* __restrict__ mean, float* __restrict__ rstd) {
    __shared__ float ss[256], sq[256];
    int head = blockIdx.x >> 8;
    int sub  = blockIdx.x & 255;
    int L = sub >> 6, c = sub & 63;
    const int voxs[4] = {32768, 4096, 512, 64};
    const int offs[4] = {0, 32768, 36864, 37376};
    int N = voxs[L];
    const float* p = (head ? b1 : b0) + c * TOT + offs[L];
    float s = 0.f, q = 0.f;
    for (int i = threadIdx.x; i < N; i += 256) {
        float x = p[i];
        s += x;
        q = fmaf(x, x, q);
    }
    ss[threadIdx.x] = s; sq[threadIdx.x] = q;
    __syncthreads();
    for (int st = 128; st > 0; st >>= 1) {
        if (threadIdx.x < st) {
            ss[threadIdx.x] += ss[threadIdx.x + st];
            sq[threadIdx.x] += sq[threadIdx.x + st];
        }
        __syncthreads();
    }
    if (threadIdx.x == 0) {
        float m = ss[0] / (float)N;
        float v = sq[0] / (float)N - m * m;
        mean[blockIdx.x] = m;
        rstd[blockIdx.x] = rsqrtf(fmaxf(v, 0.f) + 1e-5f);
    }
}

// ---------------------------------------------------------------------------
template <int LEV> struct Geo;
template <> struct Geo<0> { enum { S = 32, OFF = 0,     ZT = 4,  YT = 10, XT = 34, XP = 35 }; };
template <> struct Geo<1> { enum { S = 16, OFF = 32768, ZT = 6,  YT = 10, XT = 18, XP = 19 }; };
template <> struct Geo<2> { enum { S = 8,  OFF = 36864, ZT = 10, YT = 10, XT = 10, XP = 11 }; };
template <> struct Geo<3> { enum { S = 4,  OFF = 37376, ZT = 6,  YT = 6,  XT = 6,  XP = 7  }; };

// ---------------------------------------------------------------------------
// Conv body: BT = 128*HALVES threads. All threads cooperatively stage the
// input tile (shared across HALVES oc-groups); each 128-thread half owns one
// oc-group of OCW channels. Register-staged pipeline per ic:
//   LDG(ic+1) -> compute(ic) from smem -> STS(ic+1) -> barrier.
// All addressing hoisted out of the ic loop (ic only bumps base pointers).
// ---------------------------------------------------------------------------
template <int LEV, int OCW, int HALVES, bool FINAL, bool NORM>
__device__ __forceinline__ void conv_body(
    int sp, int ocg,
    const float* __restrict__ in, const float* __restrict__ wgt,
    const float* __restrict__ bias, float* __restrict__ out,
    const float* __restrict__ mean, const float* __restrict__ rstd,
    float alpha, int CIN, int COUT, int head_base,
    float* __restrict__ in_s, float* __restrict__ w_s) {

    typedef Geo<LEV> G;
    constexpr int S  = G::S,  OFF = G::OFF;
    constexpr int ZT = G::ZT, YT = G::YT, XT = G::XT, XP = G::XP;
    constexpr int TILE = ZT * YT * XP;
    constexpr int TOTE = ZT * YT * XT;
    constexpr int BT   = 128 * HALVES;
    constexpr int NL   = (TOTE + BT - 1) / BT;
    constexpr int WSL  = OCW * 27;
    constexpr int WPT  = (WSL + 127) / 128;

    const int t  = threadIdx.x;
    const int wg = t & 127;

    int tz, ty, tx, d0 = 0, h0 = 0;
    bool active = true;
    if (LEV == 0) { tx = wg & 7; ty = (wg >> 3) & 7; tz = wg >> 6;
                    d0 = (sp >> 2) * 2; h0 = (sp & 3) * 8; }
    else if (LEV == 1) { tx = wg & 3; ty = (wg >> 2) & 7; tz = wg >> 5;
                    d0 = (sp >> 1) * 4; h0 = (sp & 1) * 8; }
    else if (LEV == 2) { tx = wg & 1; ty = (wg >> 1) & 7; tz = wg >> 4; }
    else { tx = 0; ty = wg & 3; tz = (wg >> 2) & 3; active = (wg < 16); }

    // ---- hoisted tile addressing (ic-invariant) ----
    int goff[NL], soff[NL];
#pragma unroll
    for (int i = 0; i < NL; ++i) {
        int idx = i * BT + t;
        goff[i] = -1; soff[i] = -1;
        if (idx < TOTE) {
            int z = idx / (YT * XT), rem = idx - z * (YT * XT);
            int y = rem / XT, x = rem - y * XT;
            soff[i] = (z * YT + y) * XP + x;
            int gz = d0 - 1 + z, gy = h0 - 1 + y, gx = x - 1;
            if ((unsigned)gz < (unsigned)S && (unsigned)gy < (unsigned)S &&
                (unsigned)gx < (unsigned)S)
                goff[i] = (gz * S + gy) * S + gx;
        }
    }
    // ---- hoisted weight addressing ----
    int wgoff[WPT], wsoff[WPT];
#pragma unroll
    for (int p = 0; p < WPT; ++p) {
        int i = p * 128 + wg;
        wgoff[p] = 0; wsoff[p] = -1;
        if (i < WSL) {
            int wj = i / 27, wk = i - wj * 27;
            wgoff[p] = (ocg * OCW + wj) * CIN * 27 + wk;
            wsoff[p] = i;
        }
    }

    float acc[OCW][4];
#pragma unroll
    for (int j = 0; j < OCW; ++j) {
        acc[j][0] = 0.f; acc[j][1] = 0.f; acc[j][2] = 0.f; acc[j][3] = 0.f;
    }

    const float* inb = in + OFF;
    float v[NL], wv[WPT], mval = 0.f, rval = 0.f;

    auto ldg_phase = [&](int ic) {
        const float* src = inb + ic * TOT;
#pragma unroll
        for (int i = 0; i < NL; ++i)
            v[i] = (goff[i] >= 0) ? __ldg(src + goff[i]) : 0.f;
        const float* wsrc = wgt + ic * 27;
#pragma unroll
        for (int p = 0; p < WPT; ++p)
            if (wsoff[p] >= 0) wv[p] = __ldg(wsrc + wgoff[p]);
        if (NORM) {
            mval = __ldg(mean + LEV * 64 + ic);
            rval = __ldg(rstd + LEV * 64 + ic);
        }
    };
    auto sts_phase = [&](int b) {
        float* dst = in_s + b * TILE;
#pragma unroll
        for (int i = 0; i < NL; ++i) {
            if (soff[i] >= 0) {
                float x = v[i];
                if (NORM && goff[i] >= 0) {
                    x = (x - mval) * rval;
                    x = x >= 0.f ? x : alpha * x;
                }
                dst[soff[i]] = x;
            }
        }
        float* wd = w_s + b * WSL;
#pragma unroll
        for (int p = 0; p < WPT; ++p)
            if (wsoff[p] >= 0) wd[wsoff[p]] = wv[p];
    };

    ldg_phase(0);
    sts_phase(0);
    __syncthreads();

    for (int ic = 0; ic < CIN; ++ic) {
        int cur = ic & 1, nb = cur ^ 1;
        if (ic + 1 < CIN) ldg_phase(ic + 1);

        if (active) {
            const float* buf = in_s + cur * TILE;
            const float* wb  = w_s + cur * WSL;
#pragma unroll
            for (int kz = 0; kz < 3; ++kz) {
#pragma unroll
                for (int ky = 0; ky < 3; ++ky) {
                    const float* ip = &buf[((tz + kz) * YT + (ty + ky)) * XP + (tx << 2)];
                    float x0 = ip[0], x1 = ip[1], x2 = ip[2];
                    float x3 = ip[3], x4 = ip[4], x5 = ip[5];
                    const float* wr = &wb[(kz * 3 + ky) * 3];
#pragma unroll
                    for (int j = 0; j < OCW; ++j) {
                        float w0 = wr[j * 27 + 0];
                        float w1 = wr[j * 27 + 1];
                        float w2 = wr[j * 27 + 2];
                        acc[j][0] = fmaf(x0, w0, acc[j][0]);
                        acc[j][1] = fmaf(x1, w0, acc[j][1]);
                        acc[j][2] = fmaf(x2, w0, acc[j][2]);
                        acc[j][3] = fmaf(x3, w0, acc[j][3]);
                        acc[j][0] = fmaf(x1, w1, acc[j][0]);
                        acc[j][1] = fmaf(x2, w1, acc[j][1]);
                        acc[j][2] = fmaf(x3, w1, acc[j][2]);
                        acc[j][3] = fmaf(x4, w1, acc[j][3]);
                        acc[j][0] = fmaf(x2, w2, acc[j][0]);
                        acc[j][1] = fmaf(x3, w2, acc[j][1]);
                        acc[j][2] = fmaf(x4, w2, acc[j][2]);
                        acc[j][3] = fmaf(x5, w2, acc[j][3]);
                    }
                }
            }
        }

        if (ic + 1 < CIN) sts_phase(nb);
        __syncthreads();
    }

    if (!active) return;
    int d = d0 + tz, h = h0 + ty, w0i = tx << 2;
    int vidx = (d * S + h) * S + w0i;
#pragma unroll
    for (int j = 0; j < OCW; ++j) {
        int oc = ocg * OCW + j;
        float b = bias[oc];
        if (FINAL) {
            int base = head_base + (OFF + vidx) * COUT + oc;
            out[base + 0 * COUT] = acc[j][0] + b;
            out[base + 1 * COUT] = acc[j][1] + b;
            out[base + 2 * COUT] = acc[j][2] + b;
            out[base + 3 * COUT] = acc[j][3] + b;
        } else {
            float* o = out + oc * TOT + OFF + vidx;
            o[0] = acc[j][0] + b;
            o[1] = acc[j][1] + b;
            o[2] = acc[j][2] + b;
            o[3] = acc[j][3] + b;
        }
    }
}

// ---------------------------------------------------------------------------
// Dual-head conv kernel. grid.x = (g0 + g1) * 74 grid-groups; groups < g0 are
// head 0. Each grid-group covers HALVES oc-groups (one per 128-thread half).
// r<64: L0 tiles; r<72: L1; r==72: L2; r==73: L3.
// ---------------------------------------------------------------------------
template <int OCW, int HALVES, bool FINAL, bool NORM>
__global__ void __launch_bounds__(128 * HALVES) conv_k(
    const float* __restrict__ in0, const float* __restrict__ in1,
    const float* __restrict__ w0, const float* __restrict__ w1,
    const float* __restrict__ b0, const float* __restrict__ b1,
    float* __restrict__ out0, float* __restrict__ out1,
    const float* __restrict__ meanA, const float* __restrict__ rstdA,
    const float* __restrict__ a0, const float* __restrict__ a1, int aidx,
    int CIN, int COUT0, int COUT1, int g0, int base1) {

    __shared__ float in_s[2 * 1400];
    __shared__ float w_s[HALVES * 2 * OCW * 27];

    int gidx = blockIdx.x / 74;
    int r    = blockIdx.x - gidx * 74;
    int half = threadIdx.x >> 7;
    int head = (gidx >= g0);
    int lg   = head ? gidx - g0 : gidx;
    int ocg  = lg * HALVES + half;

    const float* in   = head ? in1 : in0;
    const float* wgt  = head ? w1  : w0;
    const float* bias = head ? b1  : b0;
    float*       out  = head ? out1 : out0;
    const float* mean = meanA + head * 256;
    const float* rstd = rstdA + head * 256;
    float alpha = NORM ? __ldg((head ? a1 : a0) + aidx) : 0.f;
    int COUT  = head ? COUT1 : COUT0;
    int hbase = head ? base1 : 0;
    float* wsl = w_s + half * (2 * OCW * 27);

    if (r < 64)
        conv_body<0, OCW, HALVES, FINAL, NORM>(r, ocg, in, wgt, bias, out,
            mean, rstd, alpha, CIN, COUT, hbase, in_s, wsl);
    else if (r < 72)
        conv_body<1, OCW, HALVES, FINAL, NORM>(r - 64, ocg, in, wgt, bias, out,
            mean, rstd, alpha, CIN, COUT, hbase, in_s, wsl);
    else if (r == 72)
        conv_body<2, OCW, HALVES, FINAL, NORM>(0, ocg, in, wgt, bias, out,
            mean, rstd, alpha, CIN, COUT, hbase, in_s, wsl);
    else
        conv_body<3, OCW, HALVES, FINAL, NORM>(0, ocg, in, wgt, bias, out,
            mean, rstd, alpha, CIN, COUT, hbase, in_s, wsl);
}

// ---------------------------------------------------------------------------
// Host launcher: 10 launches, both heads fused per layer.
// ---------------------------------------------------------------------------
extern "C" void kernel_launch(void* const* d_in, const int* in_sizes, int n_in,
                              void* d_out, int out_size) {
    (void)in_sizes; (void)n_in; (void)out_size;

    const float* p0 = (const float*)d_in[0];
    const float* p1 = (const float*)d_in[1];
    const float* p2 = (const float*)d_in[2];
    const float* p3 = (const float*)d_in[3];

    const float* cw1   = (const float*)d_in[4];
    const float* cb1   = (const float*)d_in[5];
    const float* cw234 = (const float*)d_in[6];
    const float* cb234 = (const float*)d_in[7];
    const float* ca    = (const float*)d_in[8];
    const float* cwf   = (const float*)d_in[9];
    const float* cbf   = (const float*)d_in[10];
    const float* rw1   = (const float*)d_in[11];
    const float* rb1   = (const float*)d_in[12];
    const float* rw234 = (const float*)d_in[13];
    const float* rb234 = (const float*)d_in[14];
    const float* ra    = (const float*)d_in[15];
    const float* rwf   = (const float*)d_in[16];
    const float* rbf   = (const float*)d_in[17];

    float *in36, *buf, *mean, *rstd;
    cudaGetSymbolAddress((void**)&in36, g_in36);
    cudaGetSymbolAddress((void**)&buf,  g_buf);
    cudaGetSymbolAddress((void**)&mean, g_mean);
    cudaGetSymbolAddress((void**)&rstd, g_rstd);

    float* A0 = buf;                    // head0 ping
    float* B0 = buf + 64 * TOT;         // head0 pong
    float* A1 = buf + 2 * 64 * TOT;     // head1 ping
    float* B1 = buf + 3 * 64 * TOT;     // head1 pong
    float* out = (float*)d_out;
    const int CLS_TOTAL = TOT * 18;

    pack_kernel<<<dim3(147, 36), 256>>>(p0, p1, p2, p3, in36);

    // conv1 (36->64, raw input), both heads
    conv_k<8, 2, false, false><<<8 * 74, 256>>>(
        in36, in36, cw1, rw1, cb1, rb1, A0, A1,
        mean, rstd, ca, ra, 0, 36, 64, 64, 4, 0);
    stats2_kernel<<<512, 256>>>(A0, A1, mean, rstd);

    // conv2..4 (64->64, norm+prelu fused on load), ping-pong
    float* s0 = A0; float* d0p = B0;
    float* s1 = A1; float* d1p = B1;
    for (int i = 0; i < 3; ++i) {
        conv_k<8, 2, false, true><<<8 * 74, 256>>>(
            s0, s1, cw234 + (size_t)i * 64 * 64 * 27, rw234 + (size_t)i * 64 * 64 * 27,
            cb234 + i * 64, rb234 + i * 64, d0p, d1p,
            mean, rstd, ca, ra, i, 64, 64, 64, 4, 0);
        stats2_kernel<<<512, 256>>>(d0p, d1p, mean, rstd);
        float* t0 = s0; s0 = d0p; d0p = t0;
        float* t1 = s1; s1 = d1p; d1p = t1;
    }

    // final conv: head0 COUT=18 (3 groups), head1 COUT=54 (9 groups)
    conv_k<6, 1, true, true><<<12 * 74, 128>>>(
        s0, s1, cwf, rwf, cbf, rbf, out, out,
        mean, rstd, ca, ra, 3, 64, 18, 54, 3, CLS_TOTAL);
}

// round 5
// speedup vs baseline: 1.8919x; 1.1478x over previous
#include <cuda_runtime.h>

#define TOT 37440

__device__ float g_in36[36 * TOT];
__device__ float g_buf[2][2][64 * TOT];   // [head][pingpong]
__device__ float g_mean[512];             // [head][4 levels][64 ch]
__device__ float g_rstd[512];

// ---------------------------------------------------------------------------
__global__ void pack_kernel(const float* __restrict__ p0, const float* __restrict__ p1,
                            const float* __restrict__ p2, const float* __restrict__ p3,
                            float* __restrict__ out) {
    int c = blockIdx.y;
    int pos = blockIdx.x * 256 + threadIdx.x;
    if (pos >= TOT) return;
    const float* p; int v, voxn;
    if (pos < 32768)      { p = p0; v = pos;         voxn = 32768; }
    else if (pos < 36864) { p = p1; v = pos - 32768; voxn = 4096;  }
    else if (pos < 37376) { p = p2; v = pos - 36864; voxn = 512;   }
    else                  { p = p3; v = pos - 37376; voxn = 64;    }
    out[c * TOT + pos] = p[c * voxn + v];
}

// ---------------------------------------------------------------------------
__global__ void stats2_kernel(const float* __restrict__ b0, const float* __restrict__ b1,
                              float* __restrict__ mean, float* __restrict__ rstd) {
    __shared__ float ss[256], sq[256];
    int head = blockIdx.x >> 8;
    int sub  = blockIdx.x & 255;
    int L = sub >> 6, c = sub & 63;
    const int voxs[4] = {32768, 4096, 512, 64};
    const int offs[4] = {0, 32768, 36864, 37376};
    int N = voxs[L];
    const float* p = (head ? b1 : b0) + c * TOT + offs[L];
    float s = 0.f, q = 0.f;
    for (int i = threadIdx.x; i < N; i += 256) {
        float x = p[i];
        s += x;
        q = fmaf(x, x, q);
    }
    ss[threadIdx.x] = s; sq[threadIdx.x] = q;
    __syncthreads();
    for (int st = 128; st > 0; st >>= 1) {
        if (threadIdx.x < st) {
            ss[threadIdx.x] += ss[threadIdx.x + st];
            sq[threadIdx.x] += sq[threadIdx.x + st];
        }
        __syncthreads();
    }
    if (threadIdx.x == 0) {
        float m = ss[0] / (float)N;
        float v = sq[0] / (float)N - m * m;
        mean[blockIdx.x] = m;
        rstd[blockIdx.x] = rsqrtf(fmaxf(v, 0.f) + 1e-5f);
    }
}

// ---------------------------------------------------------------------------
// XP padded to multiple of 4 -> 16B-aligned vector LDS in compute loop.
template <int LEV> struct Geo;
template <> struct Geo<0> { enum { S = 32, OFF = 0,     ZT = 4,  YT = 10, XT = 34, XP = 36 }; };
template <> struct Geo<1> { enum { S = 16, OFF = 32768, ZT = 6,  YT = 10, XT = 18, XP = 20 }; };
template <> struct Geo<2> { enum { S = 8,  OFF = 36864, ZT = 10, YT = 10, XT = 10, XP = 12 }; };
template <> struct Geo<3> { enum { S = 4,  OFF = 37376, ZT = 6,  YT = 6,  XT = 6,  XP = 8  }; };

// ---------------------------------------------------------------------------
// Conv body. Weight smem layout transposed: [27 taps][OCP=8 oc] so the per-tap
// oc-vector is contiguous (2x LDS.128). Input rows 16B aligned (XP % 4 == 0).
// Register-staged pipeline: LDG(ic+1) -> compute(ic) -> STS(ic+1) -> barrier.
// ---------------------------------------------------------------------------
template <int LEV, int OCW, int HALVES, bool FINAL, bool NORM>
__device__ __forceinline__ void conv_body(
    int sp, int ocg,
    const float* __restrict__ in, const float* __restrict__ wgt,
    const float* __restrict__ bias, float* __restrict__ out,
    const float* __restrict__ mean, const float* __restrict__ rstd,
    float alpha, int CIN, int COUT, int head_base,
    float* __restrict__ in_s, float* __restrict__ w_s) {

    typedef Geo<LEV> G;
    constexpr int S  = G::S,  OFF = G::OFF;
    constexpr int ZT = G::ZT, YT = G::YT, XT = G::XT, XP = G::XP;
    constexpr int TILE = ZT * YT * XP;
    constexpr int TOTE = ZT * YT * XT;
    constexpr int BT   = 128 * HALVES;
    constexpr int NL   = (TOTE + BT - 1) / BT;
    constexpr int OCP  = 8;                 // padded oc per tap (vector width)
    constexpr int WSLP = 27 * OCP;          // padded weight slice
    constexpr int WPT  = (WSLP + 127) / 128;

    const int t  = threadIdx.x;
    const int wg = t & 127;

    int tz, ty, tx, d0 = 0, h0 = 0;
    bool active = true;
    if (LEV == 0) { tx = wg & 7; ty = (wg >> 3) & 7; tz = wg >> 6;
                    d0 = (sp >> 2) * 2; h0 = (sp & 3) * 8; }
    else if (LEV == 1) { tx = wg & 3; ty = (wg >> 2) & 7; tz = wg >> 5;
                    d0 = (sp >> 1) * 4; h0 = (sp & 1) * 8; }
    else if (LEV == 2) { tx = wg & 1; ty = (wg >> 1) & 7; tz = wg >> 4; }
    else { tx = 0; ty = wg & 3; tz = (wg >> 2) & 3; active = (wg < 16); }

    // ---- hoisted tile addressing (ic-invariant) ----
    int goff[NL], soff[NL];
#pragma unroll
    for (int i = 0; i < NL; ++i) {
        int idx = i * BT + t;
        goff[i] = -1; soff[i] = -1;
        if (idx < TOTE) {
            int z = idx / (YT * XT), rem = idx - z * (YT * XT);
            int y = rem / XT, x = rem - y * XT;
            soff[i] = (z * YT + y) * XP + x;
            int gz = d0 - 1 + z, gy = h0 - 1 + y, gx = x - 1;
            if ((unsigned)gz < (unsigned)S && (unsigned)gy < (unsigned)S &&
                (unsigned)gx < (unsigned)S)
                goff[i] = (gz * S + gy) * S + gx;
        }
    }
    // ---- hoisted weight addressing, transposed layout [tap][oc] ----
    int wgoff[WPT];
    bool wok[WPT];
#pragma unroll
    for (int p = 0; p < WPT; ++p) {
        int i = p * 128 + wg;
        wgoff[p] = 0; wok[p] = false;
        if (i < WSLP) {
            int k = i >> 3, j = i & 7;          // tap, oc-within-group
            int oc = ocg * OCW + j;
            if (j < OCW && oc < COUT) {
                wgoff[p] = oc * CIN * 27 + k;
                wok[p] = true;
            }
        }
    }

    float acc[OCW][4];
#pragma unroll
    for (int j = 0; j < OCW; ++j) {
        acc[j][0] = 0.f; acc[j][1] = 0.f; acc[j][2] = 0.f; acc[j][3] = 0.f;
    }

    const float* inb = in + OFF;
    float v[NL], wv[WPT], mval = 0.f, rval = 0.f;

    auto ldg_phase = [&](int ic) {
        const float* src = inb + ic * TOT;
#pragma unroll
        for (int i = 0; i < NL; ++i)
            v[i] = (goff[i] >= 0) ? __ldg(src + goff[i]) : 0.f;
        const float* wsrc = wgt + ic * 27;
#pragma unroll
        for (int p = 0; p < WPT; ++p)
            wv[p] = wok[p] ? __ldg(wsrc + wgoff[p]) : 0.f;
        if (NORM) {
            mval = __ldg(mean + LEV * 64 + ic);
            rval = __ldg(rstd + LEV * 64 + ic);
        }
    };
    auto sts_phase = [&](int b) {
        float* dst = in_s + b * TILE;
#pragma unroll
        for (int i = 0; i < NL; ++i) {
            if (soff[i] >= 0) {
                float x = v[i];
                if (NORM && goff[i] >= 0) {
                    x = (x - mval) * rval;
                    x = x >= 0.f ? x : alpha * x;
                }
                dst[soff[i]] = x;
            }
        }
        float* wd = w_s + b * WSLP;
#pragma unroll
        for (int p = 0; p < WPT; ++p) {
            int i = p * 128 + wg;
            if (i < WSLP) wd[i] = wv[p];
        }
    };

    ldg_phase(0);
    sts_phase(0);
    __syncthreads();

    for (int ic = 0; ic < CIN; ++ic) {
        int cur = ic & 1, nb = cur ^ 1;
        if (ic + 1 < CIN) ldg_phase(ic + 1);

        if (active) {
            const float* buf = in_s + cur * TILE;
            const float* wb  = w_s + cur * WSLP;
#pragma unroll
            for (int kz = 0; kz < 3; ++kz) {
#pragma unroll
                for (int ky = 0; ky < 3; ++ky) {
                    const float* ip = &buf[((tz + kz) * YT + (ty + ky)) * XP + (tx << 2)];
                    float4 xa = *(const float4*)ip;
                    float2 xb = *(const float2*)(ip + 4);
                    float x0 = xa.x, x1 = xa.y, x2 = xa.z;
                    float x3 = xa.w, x4 = xb.x, x5 = xb.y;

                    const float* wt = wb + (kz * 3 + ky) * 3 * OCP;
                    float w0a[OCP], w1a[OCP], w2a[OCP];
                    *(float4*)&w0a[0] = *(const float4*)(wt);
                    *(float4*)&w0a[4] = *(const float4*)(wt + 4);
                    *(float4*)&w1a[0] = *(const float4*)(wt + OCP);
                    *(float4*)&w1a[4] = *(const float4*)(wt + OCP + 4);
                    *(float4*)&w2a[0] = *(const float4*)(wt + 2 * OCP);
                    *(float4*)&w2a[4] = *(const float4*)(wt + 2 * OCP + 4);
#pragma unroll
                    for (int j = 0; j < OCW; ++j) {
                        float w0 = w0a[j], w1 = w1a[j], w2 = w2a[j];
                        acc[j][0] = fmaf(x0, w0, acc[j][0]);
                        acc[j][1] = fmaf(x1, w0, acc[j][1]);
                        acc[j][2] = fmaf(x2, w0, acc[j][2]);
                        acc[j][3] = fmaf(x3, w0, acc[j][3]);
                        acc[j][0] = fmaf(x1, w1, acc[j][0]);
                        acc[j][1] = fmaf(x2, w1, acc[j][1]);
                        acc[j][2] = fmaf(x3, w1, acc[j][2]);
                        acc[j][3] = fmaf(x4, w1, acc[j][3]);
                        acc[j][0] = fmaf(x2, w2, acc[j][0]);
                        acc[j][1] = fmaf(x3, w2, acc[j][1]);
                        acc[j][2] = fmaf(x4, w2, acc[j][2]);
                        acc[j][3] = fmaf(x5, w2, acc[j][3]);
                    }
                }
            }
        }

        if (ic + 1 < CIN) sts_phase(nb);
        __syncthreads();
    }

    if (!active) return;
    int d = d0 + tz, h = h0 + ty, w0i = tx << 2;
    int vidx = (d * S + h) * S + w0i;
#pragma unroll
    for (int j = 0; j < OCW; ++j) {
        int oc = ocg * OCW + j;
        if (oc >= COUT) break;
        float b = bias[oc];
        if (FINAL) {
            int base = head_base + (OFF + vidx) * COUT + oc;
            out[base + 0 * COUT] = acc[j][0] + b;
            out[base + 1 * COUT] = acc[j][1] + b;
            out[base + 2 * COUT] = acc[j][2] + b;
            out[base + 3 * COUT] = acc[j][3] + b;
        } else {
            float* o = out + oc * TOT + OFF + vidx;
            o[0] = acc[j][0] + b;
            o[1] = acc[j][1] + b;
            o[2] = acc[j][2] + b;
            o[3] = acc[j][3] + b;
        }
    }
}

// ---------------------------------------------------------------------------
template <int OCW, int HALVES, bool FINAL, bool NORM>
__global__ void __launch_bounds__(128 * HALVES) conv_k(
    const float* __restrict__ in0, const float* __restrict__ in1,
    const float* __restrict__ w0, const float* __restrict__ w1,
    const float* __restrict__ b0, const float* __restrict__ b1,
    float* __restrict__ out0, float* __restrict__ out1,
    const float* __restrict__ meanA, const float* __restrict__ rstdA,
    const float* __restrict__ a0, const float* __restrict__ a1, int aidx,
    int CIN, int COUT0, int COUT1, int g0, int base1) {

    __shared__ __align__(16) float in_s[2 * 1440];
    __shared__ __align__(16) float w_s[HALVES * 2 * 27 * 8];

    int gidx = blockIdx.x / 74;
    int r    = blockIdx.x - gidx * 74;
    int half = threadIdx.x >> 7;
    int head = (gidx >= g0);
    int lg   = head ? gidx - g0 : gidx;
    int ocg  = lg * HALVES + half;

    const float* in   = head ? in1 : in0;
    const float* wgt  = head ? w1  : w0;
    const float* bias = head ? b1  : b0;
    float*       out  = head ? out1 : out0;
    const float* mean = meanA + head * 256;
    const float* rstd = rstdA + head * 256;
    float alpha = NORM ? __ldg((head ? a1 : a0) + aidx) : 0.f;
    int COUT  = head ? COUT1 : COUT0;
    int hbase = head ? base1 : 0;
    float* wsl = w_s + half * (2 * 27 * 8);

    if (r < 64)
        conv_body<0, OCW, HALVES, FINAL, NORM>(r, ocg, in, wgt, bias, out,
            mean, rstd, alpha, CIN, COUT, hbase, in_s, wsl);
    else if (r < 72)
        conv_body<1, OCW, HALVES, FINAL, NORM>(r - 64, ocg, in, wgt, bias, out,
            mean, rstd, alpha, CIN, COUT, hbase, in_s, wsl);
    else if (r == 72)
        conv_body<2, OCW, HALVES, FINAL, NORM>(0, ocg, in, wgt, bias, out,
            mean, rstd, alpha, CIN, COUT, hbase, in_s, wsl);
    else
        conv_body<3, OCW, HALVES, FINAL, NORM>(0, ocg, in, wgt, bias, out,
            mean, rstd, alpha, CIN, COUT, hbase, in_s, wsl);
}

// ---------------------------------------------------------------------------
extern "C" void kernel_launch(void* const* d_in, const int* in_sizes, int n_in,
                              void* d_out, int out_size) {
    (void)in_sizes; (void)n_in; (void)out_size;

    const float* p0 = (const float*)d_in[0];
    const float* p1 = (const float*)d_in[1];
    const float* p2 = (const float*)d_in[2];
    const float* p3 = (const float*)d_in[3];

    const float* cw1   = (const float*)d_in[4];
    const float* cb1   = (const float*)d_in[5];
    const float* cw234 = (const float*)d_in[6];
    const float* cb234 = (const float*)d_in[7];
    const float* ca    = (const float*)d_in[8];
    const float* cwf   = (const float*)d_in[9];
    const float* cbf   = (const float*)d_in[10];
    const float* rw1   = (const float*)d_in[11];
    const float* rb1   = (const float*)d_in[12];
    const float* rw234 = (const float*)d_in[13];
    const float* rb234 = (const float*)d_in[14];
    const float* ra    = (const float*)d_in[15];
    const float* rwf   = (const float*)d_in[16];
    const float* rbf   = (const float*)d_in[17];

    float *in36, *buf, *mean, *rstd;
    cudaGetSymbolAddress((void**)&in36, g_in36);
    cudaGetSymbolAddress((void**)&buf,  g_buf);
    cudaGetSymbolAddress((void**)&mean, g_mean);
    cudaGetSymbolAddress((void**)&rstd, g_rstd);

    float* A0 = buf;
    float* B0 = buf + 64 * TOT;
    float* A1 = buf + 2 * 64 * TOT;
    float* B1 = buf + 3 * 64 * TOT;
    float* out = (float*)d_out;
    const int CLS_TOTAL = TOT * 18;

    pack_kernel<<<dim3(147, 36), 256>>>(p0, p1, p2, p3, in36);

    conv_k<8, 2, false, false><<<8 * 74, 256>>>(
        in36, in36, cw1, rw1, cb1, rb1, A0, A1,
        mean, rstd, ca, ra, 0, 36, 64, 64, 4, 0);
    stats2_kernel<<<512, 256>>>(A0, A1, mean, rstd);

    float* s0 = A0; float* d0p = B0;
    float* s1 = A1; float* d1p = B1;
    for (int i = 0; i < 3; ++i) {
        conv_k<8, 2, false, true><<<8 * 74, 256>>>(
            s0, s1, cw234 + (size_t)i * 64 * 64 * 27, rw234 + (size_t)i * 64 * 64 * 27,
            cb234 + i * 64, rb234 + i * 64, d0p, d1p,
            mean, rstd, ca, ra, i, 64, 64, 64, 4, 0);
        stats2_kernel<<<512, 256>>>(d0p, d1p, mean, rstd);
        float* t0 = s0; s0 = d0p; d0p = t0;
        float* t1 = s1; s1 = d1p; d1p = t1;
    }

    conv_k<6, 1, true, true><<<12 * 74, 128>>>(
        s0, s1, cwf, rwf, cbf, rbf, out, out,
        mean, rstd, ca, ra, 3, 64, 18, 54, 3, CLS_TOTAL);
}

// round 6
// speedup vs baseline: 1.9661x; 1.0392x over previous
#include <cuda_runtime.h>

#define TOT 37440

__device__ float g_in36[36 * TOT];
__device__ float g_buf[2][2][64 * TOT];   // [head][pingpong]
__device__ float g_mean[512];             // [head][4 levels][64 ch]
__device__ float g_rstd[512];

// ---------------------------------------------------------------------------
__global__ void pack_kernel(const float* __restrict__ p0, const float* __restrict__ p1,
                            const float* __restrict__ p2, const float* __restrict__ p3,
                            float* __restrict__ out) {
    int c = blockIdx.y;
    int pos = blockIdx.x * 256 + threadIdx.x;
    if (pos >= TOT) return;
    const float* p; int v, voxn;
    if (pos < 32768)      { p = p0; v = pos;         voxn = 32768; }
    else if (pos < 36864) { p = p1; v = pos - 32768; voxn = 4096;  }
    else if (pos < 37376) { p = p2; v = pos - 36864; voxn = 512;   }
    else                  { p = p3; v = pos - 37376; voxn = 64;    }
    out[c * TOT + pos] = p[c * voxn + v];
}

// ---------------------------------------------------------------------------
__global__ void stats2_kernel(const float* __restrict__ b0, const float* __restrict__ b1,
                              float* __restrict__ mean, float* __restrict__ rstd) {
    __shared__ float ss[256], sq[256];
    int head = blockIdx.x >> 8;
    int sub  = blockIdx.x & 255;
    int L = sub >> 6, c = sub & 63;
    const int voxs[4] = {32768, 4096, 512, 64};
    const int offs[4] = {0, 32768, 36864, 37376};
    int N = voxs[L];
    const float* p = (head ? b1 : b0) + c * TOT + offs[L];
    float s = 0.f, q = 0.f;
    for (int i = threadIdx.x; i < N; i += 256) {
        float x = p[i];
        s += x;
        q = fmaf(x, x, q);
    }
    ss[threadIdx.x] = s; sq[threadIdx.x] = q;
    __syncthreads();
    for (int st = 128; st > 0; st >>= 1) {
        if (threadIdx.x < st) {
            ss[threadIdx.x] += ss[threadIdx.x + st];
            sq[threadIdx.x] += sq[threadIdx.x + st];
        }
        __syncthreads();
    }
    if (threadIdx.x == 0) {
        float m = ss[0] / (float)N;
        float v = sq[0] / (float)N - m * m;
        mean[blockIdx.x] = m;
        rstd[blockIdx.x] = rsqrtf(fmaxf(v, 0.f) + 1e-5f);
    }
}

// ---------------------------------------------------------------------------
// VW=4 geometry (final conv path, 74 spatial tiles).
template <int LEV> struct Geo4;
template <> struct Geo4<0> { enum { S = 32, OFF = 0,     ZT = 4,  YT = 10, XT = 34, XP = 36 }; };
template <> struct Geo4<1> { enum { S = 16, OFF = 32768, ZT = 6,  YT = 10, XT = 18, XP = 20 }; };
template <> struct Geo4<2> { enum { S = 8,  OFF = 36864, ZT = 10, YT = 10, XT = 10, XP = 12 }; };
template <> struct Geo4<3> { enum { S = 4,  OFF = 37376, ZT = 6,  YT = 6,  XT = 6,  XP = 8  }; };

// VW=8 geometry (main conv path, 38 spatial tiles of 1024 voxels).
template <int LEV> struct Geo8;
template <> struct Geo8<0> { enum { S = 32, OFF = 0,     ZT = 6,  YT = 10, XT = 34, XP = 36 }; };
template <> struct Geo8<1> { enum { S = 16, OFF = 32768, ZT = 6,  YT = 18, XT = 18, XP = 20 }; };
template <> struct Geo8<2> { enum { S = 8,  OFF = 36864, ZT = 10, YT = 10, XT = 10, XP = 12 }; };
template <> struct Geo8<3> { enum { S = 4,  OFF = 37376, ZT = 6,  YT = 6,  XT = 6,  XP = 12 }; };

// ---------------------------------------------------------------------------
// VW=8 conv body. 256 threads (2 halves x 8 oc); each active thread computes
// 8 consecutive W voxels x 8 oc. Weight smem transposed [tap][8 oc].
// Register-staged pipeline: LDG(ic+1) -> compute(ic) -> STS(ic+1) -> barrier.
// ---------------------------------------------------------------------------
template <int LEV, bool NORM>
__device__ __forceinline__ void conv_body8(
    int sp, int ocg,
    const float* __restrict__ in, const float* __restrict__ wgt,
    const float* __restrict__ bias, float* __restrict__ out,
    const float* __restrict__ mean, const float* __restrict__ rstd,
    float alpha, int CIN,
    float* __restrict__ in_s, float* __restrict__ w_s) {

    typedef Geo8<LEV> G;
    constexpr int S  = G::S,  OFF = G::OFF;
    constexpr int ZT = G::ZT, YT = G::YT, XT = G::XT, XP = G::XP;
    constexpr int TILE = ZT * YT * XP;
    constexpr int TOTE = ZT * YT * XT;
    constexpr int NL   = (TOTE + 255) / 256;
    constexpr int OCP  = 8;
    constexpr int WSLP = 27 * OCP;
    constexpr int WPT  = (WSLP + 127) / 128;
    constexpr int VV   = (LEV == 3) ? 4 : 8;   // valid voxels stored

    const int t  = threadIdx.x;
    const int wg = t & 127;

    int tz, ty, tx, d0 = 0, h0 = 0;
    bool active = true;
    if (LEV == 0) { tx = wg & 3; ty = (wg >> 2) & 7; tz = wg >> 5;
                    d0 = (sp >> 2) * 4; h0 = (sp & 3) * 8; }
    else if (LEV == 1) { tx = wg & 1; ty = (wg >> 1) & 15; tz = wg >> 5;
                    d0 = sp * 4; }
    else if (LEV == 2) { tx = 0; ty = wg & 7; tz = (wg >> 3) & 7; active = (wg < 64); }
    else { tx = 0; ty = wg & 3; tz = (wg >> 2) & 3; active = (wg < 16); }

    // hoisted tile addressing (ic-invariant)
    int goff[NL], soff[NL];
#pragma unroll
    for (int i = 0; i < NL; ++i) {
        int idx = i * 256 + t;
        goff[i] = -1; soff[i] = -1;
        if (idx < TOTE) {
            int z = idx / (YT * XT), rem = idx - z * (YT * XT);
            int y = rem / XT, x = rem - y * XT;
            soff[i] = (z * YT + y) * XP + x;
            int gz = d0 - 1 + z, gy = h0 - 1 + y, gx = x - 1;
            if ((unsigned)gz < (unsigned)S && (unsigned)gy < (unsigned)S &&
                (unsigned)gx < (unsigned)S)
                goff[i] = (gz * S + gy) * S + gx;
        }
    }
    // hoisted weight addressing, layout [tap][oc]
    int wgoff[WPT];
    bool wok[WPT];
#pragma unroll
    for (int p = 0; p < WPT; ++p) {
        int i = p * 128 + wg;
        wgoff[p] = 0; wok[p] = false;
        if (i < WSLP) {
            int k = i >> 3, j = i & 7;
            wgoff[p] = (ocg * 8 + j) * CIN * 27 + k;
            wok[p] = true;
        }
    }

    float acc[8][8];
#pragma unroll
    for (int j = 0; j < 8; ++j)
#pragma unroll
        for (int k = 0; k < 8; ++k) acc[j][k] = 0.f;

    const float* inb = in + OFF;
    float v[NL], wv[WPT], mval = 0.f, rval = 0.f;

    auto ldg_phase = [&](int ic) {
        const float* src = inb + ic * TOT;
#pragma unroll
        for (int i = 0; i < NL; ++i)
            v[i] = (goff[i] >= 0) ? __ldg(src + goff[i]) : 0.f;
        const float* wsrc = wgt + ic * 27;
#pragma unroll
        for (int p = 0; p < WPT; ++p)
            wv[p] = wok[p] ? __ldg(wsrc + wgoff[p]) : 0.f;
        if (NORM) {
            mval = __ldg(mean + LEV * 64 + ic);
            rval = __ldg(rstd + LEV * 64 + ic);
        }
    };
    auto sts_phase = [&](int b) {
        float* dst = in_s + b * TILE;
#pragma unroll
        for (int i = 0; i < NL; ++i) {
            if (soff[i] >= 0) {
                float x = v[i];
                if (NORM && goff[i] >= 0) {
                    x = (x - mval) * rval;
                    x = x >= 0.f ? x : alpha * x;
                }
                dst[soff[i]] = x;
            }
        }
        float* wd = w_s + b * WSLP;
#pragma unroll
        for (int p = 0; p < WPT; ++p) {
            int i = p * 128 + wg;
            if (i < WSLP) wd[i] = wv[p];
        }
    };

    ldg_phase(0);
    sts_phase(0);
    __syncthreads();

    const int x0 = tx << 3;
    for (int ic = 0; ic < CIN; ++ic) {
        int cur = ic & 1, nb = cur ^ 1;
        if (ic + 1 < CIN) ldg_phase(ic + 1);

        if (active) {
            const float* buf = in_s + cur * TILE;
            const float* wb  = w_s + cur * WSLP;
#pragma unroll
            for (int kz = 0; kz < 3; ++kz) {
#pragma unroll
                for (int ky = 0; ky < 3; ++ky) {
                    const float* ip = &buf[((tz + kz) * YT + (ty + ky)) * XP + x0];
                    float4 xa = *(const float4*)ip;
                    float4 xb = *(const float4*)(ip + 4);
                    float2 xc = *(const float2*)(ip + 8);
                    float x[10] = {xa.x, xa.y, xa.z, xa.w,
                                   xb.x, xb.y, xb.z, xb.w, xc.x, xc.y};

                    const float* wt = wb + (kz * 3 + ky) * 3 * OCP;
                    float w0a[8], w1a[8], w2a[8];
                    *(float4*)&w0a[0] = *(const float4*)(wt);
                    *(float4*)&w0a[4] = *(const float4*)(wt + 4);
                    *(float4*)&w1a[0] = *(const float4*)(wt + OCP);
                    *(float4*)&w1a[4] = *(const float4*)(wt + OCP + 4);
                    *(float4*)&w2a[0] = *(const float4*)(wt + 2 * OCP);
                    *(float4*)&w2a[4] = *(const float4*)(wt + 2 * OCP + 4);
#pragma unroll
                    for (int j = 0; j < 8; ++j) {
                        float w0 = w0a[j], w1 = w1a[j], w2 = w2a[j];
#pragma unroll
                        for (int k = 0; k < 8; ++k) {
                            acc[j][k] = fmaf(x[k],     w0, acc[j][k]);
                            acc[j][k] = fmaf(x[k + 1], w1, acc[j][k]);
                            acc[j][k] = fmaf(x[k + 2], w2, acc[j][k]);
                        }
                    }
                }
            }
        }

        if (ic + 1 < CIN) sts_phase(nb);
        __syncthreads();
    }

    if (!active) return;
    int d = d0 + tz, h = h0 + ty;
    int vidx = (d * S + h) * S + x0;
#pragma unroll
    for (int j = 0; j < 8; ++j) {
        int oc = ocg * 8 + j;
        float b = bias[oc];
        float* o = out + oc * TOT + OFF + vidx;
#pragma unroll
        for (int k = 0; k < VV; ++k) o[k] = acc[j][k] + b;
    }
}

// ---------------------------------------------------------------------------
// Main conv kernel (VW=8). grid.x = (g0+g1)*38; 256 threads (2 halves).
// r<32: L0 tiles; r<36: L1; r==36: L2; r==37: L3.
// ---------------------------------------------------------------------------
template <bool NORM>
__global__ void __launch_bounds__(256, 2) conv_k8(
    const float* __restrict__ in0, const float* __restrict__ in1,
    const float* __restrict__ w0, const float* __restrict__ w1,
    const float* __restrict__ b0, const float* __restrict__ b1,
    float* __restrict__ out0, float* __restrict__ out1,
    const float* __restrict__ meanA, const float* __restrict__ rstdA,
    const float* __restrict__ a0, const float* __restrict__ a1, int aidx,
    int CIN, int g0) {

    __shared__ __align__(16) float in_s[2 * 2160];
    __shared__ __align__(16) float w_s[2 * 2 * 27 * 8];

    int gidx = blockIdx.x / 38;
    int r    = blockIdx.x - gidx * 38;
    int half = threadIdx.x >> 7;
    int head = (gidx >= g0);
    int lg   = head ? gidx - g0 : gidx;
    int ocg  = lg * 2 + half;

    const float* in   = head ? in1 : in0;
    const float* wgt  = head ? w1  : w0;
    const float* bias = head ? b1  : b0;
    float*       out  = head ? out1 : out0;
    const float* mean = meanA + head * 256;
    const float* rstd = rstdA + head * 256;
    float alpha = NORM ? __ldg((head ? a1 : a0) + aidx) : 0.f;
    float* wsl = w_s + half * (2 * 27 * 8);

    if (r < 32)
        conv_body8<0, NORM>(r, ocg, in, wgt, bias, out, mean, rstd, alpha, CIN, in_s, wsl);
    else if (r < 36)
        conv_body8<1, NORM>(r - 32, ocg, in, wgt, bias, out, mean, rstd, alpha, CIN, in_s, wsl);
    else if (r == 36)
        conv_body8<2, NORM>(0, ocg, in, wgt, bias, out, mean, rstd, alpha, CIN, in_s, wsl);
    else
        conv_body8<3, NORM>(0, ocg, in, wgt, bias, out, mean, rstd, alpha, CIN, in_s, wsl);
}

// ---------------------------------------------------------------------------
// VW=4 conv body (final conv). 128 threads; 4 voxels x OCW oc per thread.
// ---------------------------------------------------------------------------
template <int LEV, int OCW, bool NORM>
__device__ __forceinline__ void conv_body4(
    int sp, int ocg,
    const float* __restrict__ in, const float* __restrict__ wgt,
    const float* __restrict__ bias, float* __restrict__ out,
    const float* __restrict__ mean, const float* __restrict__ rstd,
    float alpha, int CIN, int COUT, int head_base,
    float* __restrict__ in_s, float* __restrict__ w_s) {

    typedef Geo4<LEV> G;
    constexpr int S  = G::S,  OFF = G::OFF;
    constexpr int ZT = G::ZT, YT = G::YT, XT = G::XT, XP = G::XP;
    constexpr int TILE = ZT * YT * XP;
    constexpr int TOTE = ZT * YT * XT;
    constexpr int NL   = (TOTE + 127) / 128;
    constexpr int OCP  = 8;
    constexpr int WSLP = 27 * OCP;
    constexpr int WPT  = (WSLP + 127) / 128;

    const int t = threadIdx.x;
    int tz, ty, tx, d0 = 0, h0 = 0;
    bool active = true;
    if (LEV == 0) { tx = t & 7; ty = (t >> 3) & 7; tz = t >> 6;
                    d0 = (sp >> 2) * 2; h0 = (sp & 3) * 8; }
    else if (LEV == 1) { tx = t & 3; ty = (t >> 2) & 7; tz = t >> 5;
                    d0 = (sp >> 1) * 4; h0 = (sp & 1) * 8; }
    else if (LEV == 2) { tx = t & 1; ty = (t >> 1) & 7; tz = t >> 4; }
    else { tx = 0; ty = t & 3; tz = (t >> 2) & 3; active = (t < 16); }

    int goff[NL], soff[NL];
#pragma unroll
    for (int i = 0; i < NL; ++i) {
        int idx = i * 128 + t;
        goff[i] = -1; soff[i] = -1;
        if (idx < TOTE) {
            int z = idx / (YT * XT), rem = idx - z * (YT * XT);
            int y = rem / XT, x = rem - y * XT;
            soff[i] = (z * YT + y) * XP + x;
            int gz = d0 - 1 + z, gy = h0 - 1 + y, gx = x - 1;
            if ((unsigned)gz < (unsigned)S && (unsigned)gy < (unsigned)S &&
                (unsigned)gx < (unsigned)S)
                goff[i] = (gz * S + gy) * S + gx;
        }
    }
    int wgoff[WPT];
    bool wok[WPT];
#pragma unroll
    for (int p = 0; p < WPT; ++p) {
        int i = p * 128 + t;
        wgoff[p] = 0; wok[p] = false;
        if (i < WSLP) {
            int k = i >> 3, j = i & 7;
            int oc = ocg * OCW + j;
            if (j < OCW && oc < COUT) {
                wgoff[p] = oc * CIN * 27 + k;
                wok[p] = true;
            }
        }
    }

    float acc[OCW][4];
#pragma unroll
    for (int j = 0; j < OCW; ++j) {
        acc[j][0] = 0.f; acc[j][1] = 0.f; acc[j][2] = 0.f; acc[j][3] = 0.f;
    }

    const float* inb = in + OFF;
    float v[NL], wv[WPT], mval = 0.f, rval = 0.f;

    auto ldg_phase = [&](int ic) {
        const float* src = inb + ic * TOT;
#pragma unroll
        for (int i = 0; i < NL; ++i)
            v[i] = (goff[i] >= 0) ? __ldg(src + goff[i]) : 0.f;
        const float* wsrc = wgt + ic * 27;
#pragma unroll
        for (int p = 0; p < WPT; ++p)
            wv[p] = wok[p] ? __ldg(wsrc + wgoff[p]) : 0.f;
        if (NORM) {
            mval = __ldg(mean + LEV * 64 + ic);
            rval = __ldg(rstd + LEV * 64 + ic);
        }
    };
    auto sts_phase = [&](int b) {
        float* dst = in_s + b * TILE;
#pragma unroll
        for (int i = 0; i < NL; ++i) {
            if (soff[i] >= 0) {
                float x = v[i];
                if (NORM && goff[i] >= 0) {
                    x = (x - mval) * rval;
                    x = x >= 0.f ? x : alpha * x;
                }
                dst[soff[i]] = x;
            }
        }
        float* wd = w_s + b * WSLP;
#pragma unroll
        for (int p = 0; p < WPT; ++p) {
            int i = p * 128 + t;
            if (i < WSLP) wd[i] = wv[p];
        }
    };

    ldg_phase(0);
    sts_phase(0);
    __syncthreads();

    for (int ic = 0; ic < CIN; ++ic) {
        int cur = ic & 1, nb = cur ^ 1;
        if (ic + 1 < CIN) ldg_phase(ic + 1);

        if (active) {
            const float* buf = in_s + cur * TILE;
            const float* wb  = w_s + cur * WSLP;
#pragma unroll
            for (int kz = 0; kz < 3; ++kz) {
#pragma unroll
                for (int ky = 0; ky < 3; ++ky) {
                    const float* ip = &buf[((tz + kz) * YT + (ty + ky)) * XP + (tx << 2)];
                    float4 xa = *(const float4*)ip;
                    float2 xb = *(const float2*)(ip + 4);
                    float x0 = xa.x, x1 = xa.y, x2 = xa.z;
                    float x3 = xa.w, x4 = xb.x, x5 = xb.y;

                    const float* wt = wb + (kz * 3 + ky) * 3 * OCP;
                    float w0a[8], w1a[8], w2a[8];
                    *(float4*)&w0a[0] = *(const float4*)(wt);
                    *(float4*)&w0a[4] = *(const float4*)(wt + 4);
                    *(float4*)&w1a[0] = *(const float4*)(wt + OCP);
                    *(float4*)&w1a[4] = *(const float4*)(wt + OCP + 4);
                    *(float4*)&w2a[0] = *(const float4*)(wt + 2 * OCP);
                    *(float4*)&w2a[4] = *(const float4*)(wt + 2 * OCP + 4);
#pragma unroll
                    for (int j = 0; j < OCW; ++j) {
                        float w0 = w0a[j], w1 = w1a[j], w2 = w2a[j];
                        acc[j][0] = fmaf(x0, w0, acc[j][0]);
                        acc[j][1] = fmaf(x1, w0, acc[j][1]);
                        acc[j][2] = fmaf(x2, w0, acc[j][2]);
                        acc[j][3] = fmaf(x3, w0, acc[j][3]);
                        acc[j][0] = fmaf(x1, w1, acc[j][0]);
                        acc[j][1] = fmaf(x2, w1, acc[j][1]);
                        acc[j][2] = fmaf(x3, w1, acc[j][2]);
                        acc[j][3] = fmaf(x4, w1, acc[j][3]);
                        acc[j][0] = fmaf(x2, w2, acc[j][0]);
                        acc[j][1] = fmaf(x3, w2, acc[j][1]);
                        acc[j][2] = fmaf(x4, w2, acc[j][2]);
                        acc[j][3] = fmaf(x5, w2, acc[j][3]);
                    }
                }
            }
        }

        if (ic + 1 < CIN) sts_phase(nb);
        __syncthreads();
    }

    if (!active) return;
    int d = d0 + tz, h = h0 + ty, w0i = tx << 2;
    int vidx = (d * S + h) * S + w0i;
#pragma unroll
    for (int j = 0; j < OCW; ++j) {
        int oc = ocg * OCW + j;
        if (oc >= COUT) break;
        float b = bias[oc];
        int base = head_base + (OFF + vidx) * COUT + oc;
        out[base + 0 * COUT] = acc[j][0] + b;
        out[base + 1 * COUT] = acc[j][1] + b;
        out[base + 2 * COUT] = acc[j][2] + b;
        out[base + 3 * COUT] = acc[j][3] + b;
    }
}

// ---------------------------------------------------------------------------
// Final conv kernel (VW=4, channels-last output). grid.x = (g0+g1)*74.
// ---------------------------------------------------------------------------
template <int OCW>
__global__ void __launch_bounds__(128) conv_kf(
    const float* __restrict__ in0, const float* __restrict__ in1,
    const float* __restrict__ w0, const float* __restrict__ w1,
    const float* __restrict__ b0, const float* __restrict__ b1,
    float* __restrict__ out,
    const float* __restrict__ meanA, const float* __restrict__ rstdA,
    const float* __restrict__ a0, const float* __restrict__ a1, int aidx,
    int CIN, int COUT0, int COUT1, int g0, int base1) {

    __shared__ __align__(16) float in_s[2 * 1440];
    __shared__ __align__(16) float w_s[2 * 27 * 8];

    int gidx = blockIdx.x / 74;
    int r    = blockIdx.x - gidx * 74;
    int head = (gidx >= g0);
    int ocg  = head ? gidx - g0 : gidx;

    const float* in   = head ? in1 : in0;
    const float* wgt  = head ? w1  : w0;
    const float* bias = head ? b1  : b0;
    const float* mean = meanA + head * 256;
    const float* rstd = rstdA + head * 256;
    float alpha = __ldg((head ? a1 : a0) + aidx);
    int COUT  = head ? COUT1 : COUT0;
    int hbase = head ? base1 : 0;

    if (r < 64)
        conv_body4<0, OCW, true>(r, ocg, in, wgt, bias, out, mean, rstd,
                                 alpha, CIN, COUT, hbase, in_s, w_s);
    else if (r < 72)
        conv_body4<1, OCW, true>(r - 64, ocg, in, wgt, bias, out, mean, rstd,
                                 alpha, CIN, COUT, hbase, in_s, w_s);
    else if (r == 72)
        conv_body4<2, OCW, true>(0, ocg, in, wgt, bias, out, mean, rstd,
                                 alpha, CIN, COUT, hbase, in_s, w_s);
    else
        conv_body4<3, OCW, true>(0, ocg, in, wgt, bias, out, mean, rstd,
                                 alpha, CIN, COUT, hbase, in_s, w_s);
}

// ---------------------------------------------------------------------------
extern "C" void kernel_launch(void* const* d_in, const int* in_sizes, int n_in,
                              void* d_out, int out_size) {
    (void)in_sizes; (void)n_in; (void)out_size;

    const float* p0 = (const float*)d_in[0];
    const float* p1 = (const float*)d_in[1];
    const float* p2 = (const float*)d_in[2];
    const float* p3 = (const float*)d_in[3];

    const float* cw1   = (const float*)d_in[4];
    const float* cb1   = (const float*)d_in[5];
    const float* cw234 = (const float*)d_in[6];
    const float* cb234 = (const float*)d_in[7];
    const float* ca    = (const float*)d_in[8];
    const float* cwf   = (const float*)d_in[9];
    const float* cbf   = (const float*)d_in[10];
    const float* rw1   = (const float*)d_in[11];
    const float* rb1   = (const float*)d_in[12];
    const float* rw234 = (const float*)d_in[13];
    const float* rb234 = (const float*)d_in[14];
    const float* ra    = (const float*)d_in[15];
    const float* rwf   = (const float*)d_in[16];
    const float* rbf   = (const float*)d_in[17];

    float *in36, *buf, *mean, *rstd;
    cudaGetSymbolAddress((void**)&in36, g_in36);
    cudaGetSymbolAddress((void**)&buf,  g_buf);
    cudaGetSymbolAddress((void**)&mean, g_mean);
    cudaGetSymbolAddress((void**)&rstd, g_rstd);

    float* A0 = buf;
    float* B0 = buf + 64 * TOT;
    float* A1 = buf + 2 * 64 * TOT;
    float* B1 = buf + 3 * 64 * TOT;
    float* out = (float*)d_out;
    const int CLS_TOTAL = TOT * 18;

    pack_kernel<<<dim3(147, 36), 256>>>(p0, p1, p2, p3, in36);

    // conv1 (36->64, raw input), both heads: 8 grid-groups x 38 tiles
    conv_k8<false><<<8 * 38, 256>>>(
        in36, in36, cw1, rw1, cb1, rb1, A0, A1,
        mean, rstd, ca, ra, 0, 36, 4);
    stats2_kernel<<<512, 256>>>(A0, A1, mean, rstd);

    float* s0 = A0; float* d0p = B0;
    float* s1 = A1; float* d1p = B1;
    for (int i = 0; i < 3; ++i) {
        conv_k8<true><<<8 * 38, 256>>>(
            s0, s1, cw234 + (size_t)i * 64 * 64 * 27, rw234 + (size_t)i * 64 * 64 * 27,
            cb234 + i * 64, rb234 + i * 64, d0p, d1p,
            mean, rstd, ca, ra, i, 64, 4);
        stats2_kernel<<<512, 256>>>(d0p, d1p, mean, rstd);
        float* t0 = s0; s0 = d0p; d0p = t0;
        float* t1 = s1; s1 = d1p; d1p = t1;
    }

    // final conv: cls COUT=18 (3 oc-groups of 6), reg COUT=54 (9 groups of 6)
    conv_kf<6><<<12 * 74, 128>>>(
        s0, s1, cwf, rwf, cbf, rbf, out,
        mean, rstd, ca, ra, 3, 64, 18, 54, 3, CLS_TOTAL);
}

// round 8
// speedup vs baseline: 1.9762x; 1.0051x over previous
#include <cuda_runtime.h>
#include <cstdint>

// ---------------------------------------------------------------------------
// Padded layout: per level, channel-plane is (S+2)^3 with 1-voxel zero halo.
// Halos are never written -> stay zero (zero-initialized __device__ globals).
// ---------------------------------------------------------------------------
#define CST 46352   // padded channel stride = 34^3 + 18^3 + 10^3 + 6^3

__device__ float g_in36[36 * CST];
__device__ float g_buf[2][2][64 * CST];   // [head][pingpong]
__device__ float g_mean[512];             // [head][L][c]
__device__ float g_rstd[512];

__device__ __forceinline__ void cp4(uint32_t d, const float* s) {
    asm volatile("cp.async.ca.shared.global [%0], [%1], 4;" :: "r"(d), "l"(s));
}
#define CP_COMMIT() asm volatile("cp.async.commit_group;" ::: "memory")
#define CP_WAIT0()  asm volatile("cp.async.wait_group 0;" ::: "memory")

// ---------------------------------------------------------------------------
// Pack inputs into padded layout (interior only; halos stay zero).
// ---------------------------------------------------------------------------
__global__ void pack_kernel(const float* __restrict__ p0, const float* __restrict__ p1,
                            const float* __restrict__ p2, const float* __restrict__ p3,
                            float* __restrict__ out) {
    int c = blockIdx.y;
    int pos = blockIdx.x * 256 + threadIdx.x;
    if (pos >= 37440) return;
    const float* p; int v, S, PS, OF, lg;
    if (pos < 32768)      { p = p0; v = pos;         S = 32; PS = 34; OF = 0;     lg = 5; }
    else if (pos < 36864) { p = p1; v = pos - 32768; S = 16; PS = 18; OF = 39304; lg = 4; }
    else if (pos < 37376) { p = p2; v = pos - 36864; S = 8;  PS = 10; OF = 45136; lg = 3; }
    else                  { p = p3; v = pos - 37376; S = 4;  PS = 6;  OF = 46136; lg = 2; }
    int w = v & (S - 1), h = (v >> lg) & (S - 1), d = v >> (2 * lg);
    out[c * CST + OF + ((d + 1) * PS + h + 1) * PS + (w + 1)] =
        p[c * (S * S * S) + v];
}

// ---------------------------------------------------------------------------
// Per-(head,level,channel) mean/rstd over padded interior. Deterministic.
// ---------------------------------------------------------------------------
__global__ void stats2_kernel(const float* __restrict__ b0, const float* __restrict__ b1,
                              float* __restrict__ mean, float* __restrict__ rstd) {
    __shared__ float ss[256], sq[256];
    int head = blockIdx.x >> 8, sub = blockIdx.x & 255;
    int L = sub >> 6, c = sub & 63;
    const int Sv[4] = {32, 16, 8, 4}, PSv[4] = {34, 18, 10, 6};
    const int OFv[4] = {0, 39304, 45136, 46136}, lgv[4] = {5, 4, 3, 2};
    int S = Sv[L], PS = PSv[L], lg = lgv[L], N = S * S * S;
    const float* p = (head ? b1 : b0) + c * CST + OFv[L];
    float s = 0.f, q = 0.f;
    for (int i = threadIdx.x; i < N; i += 256) {
        int w = i & (S - 1), h = (i >> lg) & (S - 1), d = i >> (2 * lg);
        float x = p[((d + 1) * PS + h + 1) * PS + (w + 1)];
        s += x;
        q = fmaf(x, x, q);
    }
    ss[threadIdx.x] = s; sq[threadIdx.x] = q;
    __syncthreads();
    for (int st = 128; st > 0; st >>= 1) {
        if (threadIdx.x < st) {
            ss[threadIdx.x] += ss[threadIdx.x + st];
            sq[threadIdx.x] += sq[threadIdx.x + st];
        }
        __syncthreads();
    }
    if (threadIdx.x == 0) {
        float m = ss[0] / (float)N;
        float v = sq[0] / (float)N - m * m;
        mean[blockIdx.x] = m;
        rstd[blockIdx.x] = rsqrtf(fmaxf(v, 0.f) + 1e-5f);
    }
}

// ---------------------------------------------------------------------------
// In-place InstanceNorm + PReLU over padded interior.
// ---------------------------------------------------------------------------
__global__ void np_kernel(float* __restrict__ b0, float* __restrict__ b1,
                          const float* __restrict__ mean, const float* __restrict__ rstd,
                          const float* __restrict__ a0, const float* __restrict__ a1,
                          int aidx) {
    int head = blockIdx.x >> 8, sub = blockIdx.x & 255;
    int L = sub >> 6, c = sub & 63;
    const int Sv[4] = {32, 16, 8, 4}, PSv[4] = {34, 18, 10, 6};
    const int OFv[4] = {0, 39304, 45136, 46136}, lgv[4] = {5, 4, 3, 2};
    int S = Sv[L], PS = PSv[L], lg = lgv[L], N = S * S * S;
    float* p = (head ? b1 : b0) + c * CST + OFv[L];
    float m = mean[blockIdx.x], r = rstd[blockIdx.x];
    float alpha = __ldg((head ? a1 : a0) + aidx);
    for (int i = threadIdx.x; i < N; i += 256) {
        int w = i & (S - 1), h = (i >> lg) & (S - 1), d = i >> (2 * lg);
        int idx = ((d + 1) * PS + h + 1) * PS + (w + 1);
        float x = (p[idx] - m) * r;
        p[idx] = x >= 0.f ? x : alpha * x;
    }
}

// ---------------------------------------------------------------------------
// Geometry. XT = full padded width (S+2); XP padded to mult of 4 for LDS.128.
template <int LEV> struct Geo8;
template <> struct Geo8<0> { enum { S = 32, PS = 34, OFF = 0,     ZT = 6,  YT = 10, XT = 34, XP = 36 }; };
template <> struct Geo8<1> { enum { S = 16, PS = 18, OFF = 39304, ZT = 6,  YT = 18, XT = 18, XP = 20 }; };
template <> struct Geo8<2> { enum { S = 8,  PS = 10, OFF = 45136, ZT = 10, YT = 10, XT = 10, XP = 12 }; };
template <> struct Geo8<3> { enum { S = 4,  PS = 6,  OFF = 46136, ZT = 6,  YT = 6,  XT = 6,  XP = 12 }; };

template <int LEV> struct Geo4;
template <> struct Geo4<0> { enum { S = 32, PS = 34, OFF = 0,     VOX = 0,     ZT = 4,  YT = 10, XT = 34, XP = 36 }; };
template <> struct Geo4<1> { enum { S = 16, PS = 18, OFF = 39304, VOX = 32768, ZT = 6,  YT = 10, XT = 18, XP = 20 }; };
template <> struct Geo4<2> { enum { S = 8,  PS = 10, OFF = 45136, VOX = 36864, ZT = 10, YT = 10, XT = 10, XP = 12 }; };
template <> struct Geo4<3> { enum { S = 4,  PS = 6,  OFF = 46136, VOX = 37376, ZT = 6,  YT = 6,  XT = 6,  XP = 8  }; };

// ---------------------------------------------------------------------------
// VW=8 conv body. 256 threads = 2 halves x 8 oc. cp.async staging, padded
// layout (no bounds checks), double-buffered, one barrier per ic.
// ---------------------------------------------------------------------------
template <int LEV>
__device__ __forceinline__ void conv_body8(
    int sp, int ocg,
    const float* __restrict__ in, const float* __restrict__ wgt,
    const float* __restrict__ bias, float* __restrict__ out,
    int CIN, float* __restrict__ in_s, float* __restrict__ w_s) {

    typedef Geo8<LEV> G;
    constexpr int PS = G::PS, OFF = G::OFF;
    constexpr int ZT = G::ZT, YT = G::YT, XT = G::XT, XP = G::XP;
    constexpr int TILE = ZT * YT * XP;
    constexpr int TOTE = ZT * YT * XT;
    constexpr int NL   = (TOTE + 255) / 256;
    constexpr int VV   = (LEV == 3) ? 4 : 8;

    const int t  = threadIdx.x;
    const int wg = t & 127;

    int tz, ty, tx, d0 = 0, h0 = 0;
    bool active = true;
    if (LEV == 0) { tx = wg & 3; ty = (wg >> 2) & 7; tz = wg >> 5;
                    d0 = (sp >> 2) * 4; h0 = (sp & 3) * 8; }
    else if (LEV == 1) { tx = wg & 1; ty = (wg >> 1) & 15; tz = wg >> 5;
                    d0 = sp * 4; }
    else if (LEV == 2) { tx = 0; ty = wg & 7; tz = (wg >> 3) & 7; active = (wg < 64); }
    else { tx = 0; ty = wg & 3; tz = (wg >> 2) & 3; active = (wg < 16); }

    // hoisted tile addressing (ic-invariant)
    int goff[NL], sbyte[NL];
#pragma unroll
    for (int i = 0; i < NL; ++i) {
        int idx = i * 256 + t;
        sbyte[i] = -1;
        if (idx < TOTE) {
            int z = idx / (YT * XT), rem = idx - z * (YT * XT);
            int y = rem / XT, x = rem - y * XT;
            goff[i]  = ((d0 + z) * PS + (h0 + y)) * PS + x;
            sbyte[i] = ((z * YT + y) * XP + x) * 4;
        }
    }
    // hoisted weight addressing: 216 entries, 2 passes of 128 threads
    int wgoff[2];
    bool wok[2];
#pragma unroll
    for (int p = 0; p < 2; ++p) {
        int i = p * 128 + wg;
        wgoff[p] = 0; wok[p] = false;
        if (i < 216) {
            wgoff[p] = ((ocg * 8 + (i & 7)) * CIN) * 27 + (i >> 3);
            wok[p] = true;
        }
    }

    const uint32_t in_sa = (uint32_t)__cvta_generic_to_shared(in_s);
    const uint32_t w_sa  = (uint32_t)__cvta_generic_to_shared(w_s);

    float acc[8][8];
#pragma unroll
    for (int j = 0; j < 8; ++j)
#pragma unroll
        for (int k = 0; k < 8; ++k) acc[j][k] = 0.f;

    const float* inb = in + OFF;

    auto issue = [&](int b, int ic) {
        const float* src = inb + ic * CST;
#pragma unroll
        for (int i = 0; i < NL; ++i)
            if (sbyte[i] >= 0) cp4(in_sa + b * (TILE * 4) + sbyte[i], src + goff[i]);
#pragma unroll
        for (int p = 0; p < 2; ++p)
            if (wok[p]) cp4(w_sa + b * (216 * 4) + (p * 128 + wg) * 4,
                            wgt + ic * 27 + wgoff[p]);
    };

    issue(0, 0);
    CP_COMMIT();
    CP_WAIT0();
    __syncthreads();

    const int x0 = tx << 3;
    for (int ic = 0; ic < CIN; ++ic) {
        int cur = ic & 1, nb = cur ^ 1;
        if (ic + 1 < CIN) { issue(nb, ic + 1); CP_COMMIT(); }

        if (active) {
            const float* buf = in_s + cur * TILE;
            const float* wb  = w_s + cur * 216;
#pragma unroll
            for (int kz = 0; kz < 3; ++kz) {
#pragma unroll
                for (int ky = 0; ky < 3; ++ky) {
                    const float* ip = &buf[((tz + kz) * YT + (ty + ky)) * XP + x0];
                    float4 xa = *(const float4*)ip;
                    float4 xb = *(const float4*)(ip + 4);
                    float2 xc = *(const float2*)(ip + 8);
                    float x[10] = {xa.x, xa.y, xa.z, xa.w,
                                   xb.x, xb.y, xb.z, xb.w, xc.x, xc.y};

                    const float* wt = wb + (kz * 3 + ky) * 24;
                    float w0a[8], w1a[8], w2a[8];
                    *(float4*)&w0a[0] = *(const float4*)(wt);
                    *(float4*)&w0a[4] = *(const float4*)(wt + 4);
                    *(float4*)&w1a[0] = *(const float4*)(wt + 8);
                    *(float4*)&w1a[4] = *(const float4*)(wt + 12);
                    *(float4*)&w2a[0] = *(const float4*)(wt + 16);
                    *(float4*)&w2a[4] = *(const float4*)(wt + 20);
#pragma unroll
                    for (int j = 0; j < 8; ++j) {
                        float w0 = w0a[j], w1 = w1a[j], w2 = w2a[j];
#pragma unroll
                        for (int k = 0; k < 8; ++k) {
                            acc[j][k] = fmaf(x[k],     w0, acc[j][k]);
                            acc[j][k] = fmaf(x[k + 1], w1, acc[j][k]);
                            acc[j][k] = fmaf(x[k + 2], w2, acc[j][k]);
                        }
                    }
                }
            }
        }

        if (ic + 1 < CIN) CP_WAIT0();
        __syncthreads();
    }

    if (!active) return;
    int d = d0 + tz, h = h0 + ty;
    int pidx = ((d + 1) * PS + (h + 1)) * PS + (x0 + 1);
#pragma unroll
    for (int j = 0; j < 8; ++j) {
        int oc = ocg * 8 + j;
        float b = bias[oc];
        float* o = out + oc * CST + OFF + pidx;
#pragma unroll
        for (int k = 0; k < VV; ++k) o[k] = acc[j][k] + b;
    }
}

// ---------------------------------------------------------------------------
template <int DUMMY>
__global__ void __launch_bounds__(256, 2) conv_k8(
    const float* __restrict__ in0, const float* __restrict__ in1,
    const float* __restrict__ w0, const float* __restrict__ w1,
    const float* __restrict__ b0, const float* __restrict__ b1,
    float* __restrict__ out0, float* __restrict__ out1,
    int CIN, int g0) {

    __shared__ __align__(16) float in_s[2 * 2160];
    __shared__ __align__(16) float w_s[2 * 2 * 216];

    int gidx = blockIdx.x / 38;
    int r    = blockIdx.x - gidx * 38;
    int half = threadIdx.x >> 7;
    int head = (gidx >= g0);
    int lg   = head ? gidx - g0 : gidx;
    int ocg  = lg * 2 + half;

    const float* in   = head ? in1 : in0;
    const float* wgt  = head ? w1  : w0;
    const float* bias = head ? b1  : b0;
    float*       out  = head ? out1 : out0;
    float* wsl = w_s + half * (2 * 216);

    if (r < 32)
        conv_body8<0>(r, ocg, in, wgt, bias, out, CIN, in_s, wsl);
    else if (r < 36)
        conv_body8<1>(r - 32, ocg, in, wgt, bias, out, CIN, in_s, wsl);
    else if (r == 36)
        conv_body8<2>(0, ocg, in, wgt, bias, out, CIN, in_s, wsl);
    else
        conv_body8<3>(0, ocg, in, wgt, bias, out, CIN, in_s, wsl);
}

// ---------------------------------------------------------------------------
// VW=4 final conv body (channels-last output to d_out). 128 threads.
// ---------------------------------------------------------------------------
template <int LEV, int OCW>
__device__ __forceinline__ void conv_body4(
    int sp, int ocg,
    const float* __restrict__ in, const float* __restrict__ wgt,
    const float* __restrict__ bias, float* __restrict__ out,
    int CIN, int COUT, int head_base,
    float* __restrict__ in_s, float* __restrict__ w_s) {

    typedef Geo4<LEV> G;
    constexpr int S = G::S, PS = G::PS, OFF = G::OFF, VOX = G::VOX;
    constexpr int ZT = G::ZT, YT = G::YT, XT = G::XT, XP = G::XP;
    constexpr int TILE = ZT * YT * XP;
    constexpr int TOTE = ZT * YT * XT;
    constexpr int NL   = (TOTE + 127) / 128;

    const int t = threadIdx.x;
    int tz, ty, tx, d0 = 0, h0 = 0;
    bool active = true;
    if (LEV == 0) { tx = t & 7; ty = (t >> 3) & 7; tz = t >> 6;
                    d0 = (sp >> 2) * 2; h0 = (sp & 3) * 8; }
    else if (LEV == 1) { tx = t & 3; ty = (t >> 2) & 7; tz = t >> 5;
                    d0 = (sp >> 1) * 4; h0 = (sp & 1) * 8; }
    else if (LEV == 2) { tx = t & 1; ty = (t >> 1) & 7; tz = t >> 4; }
    else { tx = 0; ty = t & 3; tz = (t >> 2) & 3; active = (t < 16); }

    int goff[NL], sbyte[NL];
#pragma unroll
    for (int i = 0; i < NL; ++i) {
        int idx = i * 128 + t;
        sbyte[i] = -1;
        if (idx < TOTE) {
            int z = idx / (YT * XT), rem = idx - z * (YT * XT);
            int y = rem / XT, x = rem - y * XT;
            goff[i]  = ((d0 + z) * PS + (h0 + y)) * PS + x;
            sbyte[i] = ((z * YT + y) * XP + x) * 4;
        }
    }
    int wgoff[2];
    bool wok[2];
#pragma unroll
    for (int p = 0; p < 2; ++p) {
        int i = p * 128 + t;
        wgoff[p] = 0; wok[p] = false;
        if (i < 216) {
            int k = i >> 3, j = i & 7;
            int oc = ocg * OCW + j;
            if (j < OCW && oc < COUT) {
                wgoff[p] = (oc * CIN) * 27 + k;
                wok[p] = true;
            }
        }
    }

    const uint32_t in_sa = (uint32_t)__cvta_generic_to_shared(in_s);
    const uint32_t w_sa  = (uint32_t)__cvta_generic_to_shared(w_s);

    float acc[OCW][4];
#pragma unroll
    for (int j = 0; j < OCW; ++j) {
        acc[j][0] = 0.f; acc[j][1] = 0.f; acc[j][2] = 0.f; acc[j][3] = 0.f;
    }

    const float* inb = in + OFF;

    // zero the (never-loaded) padded weight slots once (j >= OCW entries)
    for (int i = t; i < 2 * 216; i += 128) w_s[i] = 0.f;
    __syncthreads();

    auto issue = [&](int b, int ic) {
        const float* src = inb + ic * CST;
#pragma unroll
        for (int i = 0; i < NL; ++i)
            if (sbyte[i] >= 0) cp4(in_sa + b * (TILE * 4) + sbyte[i], src + goff[i]);
#pragma unroll
        for (int p = 0; p < 2; ++p)
            if (wok[p]) cp4(w_sa + b * (216 * 4) + (p * 128 + t) * 4,
                            wgt + ic * 27 + wgoff[p]);
    };

    issue(0, 0);
    CP_COMMIT();
    CP_WAIT0();
    __syncthreads();

    for (int ic = 0; ic < CIN; ++ic) {
        int cur = ic & 1, nb = cur ^ 1;
        if (ic + 1 < CIN) { issue(nb, ic + 1); CP_COMMIT(); }

        if (active) {
            const float* buf = in_s + cur * TILE;
            const float* wb  = w_s + cur * 216;
#pragma unroll
            for (int kz = 0; kz < 3; ++kz) {
#pragma unroll
                for (int ky = 0; ky < 3; ++ky) {
                    const float* ip = &buf[((tz + kz) * YT + (ty + ky)) * XP + (tx << 2)];
                    float4 xa = *(const float4*)ip;
                    float2 xb = *(const float2*)(ip + 4);
                    float x0 = xa.x, x1 = xa.y, x2 = xa.z;
                    float x3 = xa.w, x4 = xb.x, x5 = xb.y;

                    const float* wt = wb + (kz * 3 + ky) * 24;
                    float w0a[8], w1a[8], w2a[8];
                    *(float4*)&w0a[0] = *(const float4*)(wt);
                    *(float4*)&w0a[4] = *(const float4*)(wt + 4);
                    *(float4*)&w1a[0] = *(const float4*)(wt + 8);
                    *(float4*)&w1a[4] = *(const float4*)(wt + 12);
                    *(float4*)&w2a[0] = *(const float4*)(wt + 16);
                    *(float4*)&w2a[4] = *(const float4*)(wt + 20);
#pragma unroll
                    for (int j = 0; j < OCW; ++j) {
                        float w0 = w0a[j], w1 = w1a[j], w2 = w2a[j];
                        acc[j][0] = fmaf(x0, w0, acc[j][0]);
                        acc[j][1] = fmaf(x1, w0, acc[j][1]);
                        acc[j][2] = fmaf(x2, w0, acc[j][2]);
                        acc[j][3] = fmaf(x3, w0, acc[j][3]);
                        acc[j][0] = fmaf(x1, w1, acc[j][0]);
                        acc[j][1] = fmaf(x2, w1, acc[j][1]);
                        acc[j][2] = fmaf(x3, w1, acc[j][2]);
                        acc[j][3] = fmaf(x4, w1, acc[j][3]);
                        acc[j][0] = fmaf(x2, w2, acc[j][0]);
                        acc[j][1] = fmaf(x3, w2, acc[j][1]);
                        acc[j][2] = fmaf(x4, w2, acc[j][2]);
                        acc[j][3] = fmaf(x5, w2, acc[j][3]);
                    }
                }
            }
        }

        if (ic + 1 < CIN) CP_WAIT0();
        __syncthreads();
    }

    if (!active) return;
    int d = d0 + tz, h = h0 + ty, w0i = tx << 2;
    int vidx = (d * S + h) * S + w0i;
#pragma unroll
    for (int j = 0; j < OCW; ++j) {
        int oc = ocg * OCW + j;
        if (oc >= COUT) break;
        float b = bias[oc];
        int base = head_base + (VOX + vidx) * COUT + oc;
        out[base + 0 * COUT] = acc[j][0] + b;
        out[base + 1 * COUT] = acc[j][1] + b;
        out[base + 2 * COUT] = acc[j][2] + b;
        out[base + 3 * COUT] = acc[j][3] + b;
    }
}

// ---------------------------------------------------------------------------
template <int OCW>
__global__ void __launch_bounds__(128) conv_kf(
    const float* __restrict__ in0, const float* __restrict__ in1,
    const float* __restrict__ w0, const float* __restrict__ w1,
    const float* __restrict__ b0, const float* __restrict__ b1,
    float* __restrict__ out,
    int CIN, int COUT0, int COUT1, int g0, int base1) {

    __shared__ __align__(16) float in_s[2 * 1440];
    __shared__ __align__(16) float w_s[2 * 216];

    int gidx = blockIdx.x / 74;
    int r    = blockIdx.x - gidx * 74;
    int head = (gidx >= g0);
    int ocg  = head ? gidx - g0 : gidx;

    const float* in   = head ? in1 : in0;
    const float* wgt  = head ? w1  : w0;
    const float* bias = head ? b1  : b0;
    int COUT  = head ? COUT1 : COUT0;
    int hbase = head ? base1 : 0;

    if (r < 64)
        conv_body4<0, OCW>(r, ocg, in, wgt, bias, out, CIN, COUT, hbase, in_s, w_s);
    else if (r < 72)
        conv_body4<1, OCW>(r - 64, ocg, in, wgt, bias, out, CIN, COUT, hbase, in_s, w_s);
    else if (r == 72)
        conv_body4<2, OCW>(0, ocg, in, wgt, bias, out, CIN, COUT, hbase, in_s, w_s);
    else
        conv_body4<3, OCW>(0, ocg, in, wgt, bias, out, CIN, COUT, hbase, in_s, w_s);
}

// ---------------------------------------------------------------------------
extern "C" void kernel_launch(void* const* d_in, const int* in_sizes, int n_in,
                              void* d_out, int out_size) {
    (void)in_sizes; (void)n_in; (void)out_size;

    const float* p0 = (const float*)d_in[0];
    const float* p1 = (const float*)d_in[1];
    const float* p2 = (const float*)d_in[2];
    const float* p3 = (const float*)d_in[3];

    const float* cw1   = (const float*)d_in[4];
    const float* cb1   = (const float*)d_in[5];
    const float* cw234 = (const float*)d_in[6];
    const float* cb234 = (const float*)d_in[7];
    const float* ca    = (const float*)d_in[8];
    const float* cwf   = (const float*)d_in[9];
    const float* cbf   = (const float*)d_in[10];
    const float* rw1   = (const float*)d_in[11];
    const float* rb1   = (const float*)d_in[12];
    const float* rw234 = (const float*)d_in[13];
    const float* rb234 = (const float*)d_in[14];
    const float* ra    = (const float*)d_in[15];
    const float* rwf   = (const float*)d_in[16];
    const float* rbf   = (const float*)d_in[17];

    float *in36, *buf, *mean, *rstd;
    cudaGetSymbolAddress((void**)&in36, g_in36);
    cudaGetSymbolAddress((void**)&buf,  g_buf);
    cudaGetSymbolAddress((void**)&mean, g_mean);
    cudaGetSymbolAddress((void**)&rstd, g_rstd);

    float* A0 = buf;
    float* B0 = buf + (size_t)64 * CST;
    float* A1 = buf + (size_t)2 * 64 * CST;
    float* B1 = buf + (size_t)3 * 64 * CST;
    float* out = (float*)d_out;
    const int CLS_TOTAL = 37440 * 18;

    pack_kernel<<<dim3(147, 36), 256>>>(p0, p1, p2, p3, in36);

    // conv1 (36->64, raw input), both heads: 8 grid-groups x 38 tiles
    conv_k8<0><<<8 * 38, 256>>>(in36, in36, cw1, rw1, cb1, rb1, A0, A1, 36, 4);
    stats2_kernel<<<512, 256>>>(A0, A1, mean, rstd);
    np_kernel<<<512, 256>>>(A0, A1, mean, rstd, ca, ra, 0);

    float* s0 = A0; float* d0p = B0;
    float* s1 = A1; float* d1p = B1;
    for (int i = 0; i < 3; ++i) {
        conv_k8<0><<<8 * 38, 256>>>(
            s0, s1, cw234 + (size_t)i * 64 * 64 * 27, rw234 + (size_t)i * 64 * 64 * 27,
            cb234 + i * 64, rb234 + i * 64, d0p, d1p, 64, 4);
        stats2_kernel<<<512, 256>>>(d0p, d1p, mean, rstd);
        np_kernel<<<512, 256>>>(d0p, d1p, mean, rstd, ca, ra, i + 1);
        float* t0 = s0; s0 = d0p; d0p = t0;
        float* t1 = s1; s1 = d1p; d1p = t1;
    }

    // final conv: cls COUT=18 (3 oc-groups of 6), reg COUT=54 (9 groups of 6)
    conv_kf<6><<<12 * 74, 128>>>(
        s0, s1, cwf, rwf, cbf, rbf, out, 64, 18, 54, 3, CLS_TOTAL);
}

// round 9
// speedup vs baseline: 2.1499x; 1.0879x over previous
#include <cuda_runtime.h>
#include <cstdint>

// ---------------------------------------------------------------------------
// Padded layout: per level, channel-plane is (S+2)^3 with 1-voxel zero halo.
// Halos are never written -> stay zero (zero-initialized __device__ globals).
// ---------------------------------------------------------------------------
#define CST 46352   // padded channel stride = 34^3 + 18^3 + 10^3 + 6^3

__device__ float g_in36[36 * CST];
__device__ float g_buf[2][2][64 * CST];   // [head][pingpong]
__device__ float g_mean[512];             // [head][L][c]
__device__ float g_rstd[512];

__device__ __forceinline__ void cp4(uint32_t d, const float* s) {
    asm volatile("cp.async.ca.shared.global [%0], [%1], 4;" :: "r"(d), "l"(s));
}
#define CP_COMMIT() asm volatile("cp.async.commit_group;" ::: "memory")
#define CP_WAIT0()  asm volatile("cp.async.wait_group 0;" ::: "memory")

// ---------------------------------------------------------------------------
// Pack inputs into padded layout (interior only; halos stay zero).
// ---------------------------------------------------------------------------
__global__ void pack_kernel(const float* __restrict__ p0, const float* __restrict__ p1,
                            const float* __restrict__ p2, const float* __restrict__ p3,
                            float* __restrict__ out) {
    int c = blockIdx.y;
    int pos = blockIdx.x * 256 + threadIdx.x;
    if (pos >= 37440) return;
    const float* p; int v, S, PS, OF, lg;
    if (pos < 32768)      { p = p0; v = pos;         S = 32; PS = 34; OF = 0;     lg = 5; }
    else if (pos < 36864) { p = p1; v = pos - 32768; S = 16; PS = 18; OF = 39304; lg = 4; }
    else if (pos < 37376) { p = p2; v = pos - 36864; S = 8;  PS = 10; OF = 45136; lg = 3; }
    else                  { p = p3; v = pos - 37376; S = 4;  PS = 6;  OF = 46136; lg = 2; }
    int w = v & (S - 1), h = (v >> lg) & (S - 1), d = v >> (2 * lg);
    out[c * CST + OF + ((d + 1) * PS + h + 1) * PS + (w + 1)] =
        p[c * (S * S * S) + v];
}

// ---------------------------------------------------------------------------
// Per-(head,level,channel) mean/rstd. Sum over the WHOLE padded block with
// vectorized loads (halo zeros contribute 0); divide by interior count S^3.
// ---------------------------------------------------------------------------
__global__ void stats2_kernel(const float* __restrict__ b0, const float* __restrict__ b1,
                              float* __restrict__ mean, float* __restrict__ rstd) {
    __shared__ float ss[256], sq[256];
    int head = blockIdx.x >> 8, sub = blockIdx.x & 255;
    int L = sub >> 6, c = sub & 63;
    const int Nv[4]  = {32768, 4096, 512, 64};          // interior S^3
    const int P4v[4] = {9826, 1458, 250, 54};           // PS^3 / 4
    const int OFv[4] = {0, 39304, 45136, 46136};
    int n4 = P4v[L];
    const float4* p = (const float4*)((head ? b1 : b0) + c * CST + OFv[L]);
    float s = 0.f, q = 0.f;
#pragma unroll 4
    for (int i = threadIdx.x; i < n4; i += 256) {
        float4 v = p[i];
        s += v.x + v.y + v.z + v.w;
        q = fmaf(v.x, v.x, q);
        q = fmaf(v.y, v.y, q);
        q = fmaf(v.z, v.z, q);
        q = fmaf(v.w, v.w, q);
    }
    ss[threadIdx.x] = s; sq[threadIdx.x] = q;
    __syncthreads();
    for (int st = 128; st > 0; st >>= 1) {
        if (threadIdx.x < st) {
            ss[threadIdx.x] += ss[threadIdx.x + st];
            sq[threadIdx.x] += sq[threadIdx.x + st];
        }
        __syncthreads();
    }
    if (threadIdx.x == 0) {
        float m = ss[0] / (float)Nv[L];
        float v = sq[0] / (float)Nv[L] - m * m;
        mean[blockIdx.x] = m;
        rstd[blockIdx.x] = rsqrtf(fmaxf(v, 0.f) + 1e-5f);
    }
}

// ---------------------------------------------------------------------------
// In-place InstanceNorm + PReLU, fully voxel-parallel (one elem per thread).
// grid = (147, 64 channels, 2 heads).
// ---------------------------------------------------------------------------
__global__ void np_kernel(float* __restrict__ b0, float* __restrict__ b1,
                          const float* __restrict__ mean, const float* __restrict__ rstd,
                          const float* __restrict__ a0, const float* __restrict__ a1,
                          int aidx) {
    int c = blockIdx.y, head = blockIdx.z;
    int pos = blockIdx.x * 256 + threadIdx.x;
    if (pos >= 37440) return;
    int v, S, PS, OF, lg, L;
    if (pos < 32768)      { v = pos;         S = 32; PS = 34; OF = 0;     lg = 5; L = 0; }
    else if (pos < 36864) { v = pos - 32768; S = 16; PS = 18; OF = 39304; lg = 4; L = 1; }
    else if (pos < 37376) { v = pos - 36864; S = 8;  PS = 10; OF = 45136; lg = 3; L = 2; }
    else                  { v = pos - 37376; S = 4;  PS = 6;  OF = 46136; lg = 2; L = 3; }
    int w = v & (S - 1), h = (v >> lg) & (S - 1), d = v >> (2 * lg);
    float* p = (head ? b1 : b0) + c * CST + OF + ((d + 1) * PS + h + 1) * PS + (w + 1);
    int si = head * 256 + L * 64 + c;
    float m = __ldg(mean + si), r = __ldg(rstd + si);
    float alpha = __ldg((head ? a1 : a0) + aidx);
    float x = (*p - m) * r;
    *p = x >= 0.f ? x : alpha * x;
}

// ---------------------------------------------------------------------------
// Geometry. XT = full padded width (S+2); XP padded to mult of 4 for LDS.128.
template <int LEV> struct Geo8;
template <> struct Geo8<0> { enum { S = 32, PS = 34, OFF = 0,     ZT = 6,  YT = 10, XT = 34, XP = 36 }; };
template <> struct Geo8<1> { enum { S = 16, PS = 18, OFF = 39304, ZT = 6,  YT = 18, XT = 18, XP = 20 }; };
template <> struct Geo8<2> { enum { S = 8,  PS = 10, OFF = 45136, ZT = 10, YT = 10, XT = 10, XP = 12 }; };
template <> struct Geo8<3> { enum { S = 4,  PS = 6,  OFF = 46136, ZT = 6,  YT = 6,  XT = 6,  XP = 12 }; };

template <int LEV> struct Geo4;
template <> struct Geo4<0> { enum { S = 32, PS = 34, OFF = 0,     VOX = 0,     ZT = 4,  YT = 10, XT = 34, XP = 36 }; };
template <> struct Geo4<1> { enum { S = 16, PS = 18, OFF = 39304, VOX = 32768, ZT = 6,  YT = 10, XT = 18, XP = 20 }; };
template <> struct Geo4<2> { enum { S = 8,  PS = 10, OFF = 45136, VOX = 36864, ZT = 10, YT = 10, XT = 10, XP = 12 }; };
template <> struct Geo4<3> { enum { S = 4,  PS = 6,  OFF = 46136, VOX = 37376, ZT = 6,  YT = 6,  XT = 6,  XP = 8  }; };

// ---------------------------------------------------------------------------
// VW=8 conv body. 256 threads = 2 halves x 8 oc. cp.async staging, padded
// layout (no bounds checks), double-buffered, one barrier per ic.
// ---------------------------------------------------------------------------
template <int LEV>
__device__ __forceinline__ void conv_body8(
    int sp, int ocg,
    const float* __restrict__ in, const float* __restrict__ wgt,
    const float* __restrict__ bias, float* __restrict__ out,
    int CIN, float* __restrict__ in_s, float* __restrict__ w_s) {

    typedef Geo8<LEV> G;
    constexpr int PS = G::PS, OFF = G::OFF;
    constexpr int ZT = G::ZT, YT = G::YT, XT = G::XT, XP = G::XP;
    constexpr int TILE = ZT * YT * XP;
    constexpr int TOTE = ZT * YT * XT;
    constexpr int NL   = (TOTE + 255) / 256;
    constexpr int VV   = (LEV == 3) ? 4 : 8;

    const int t  = threadIdx.x;
    const int wg = t & 127;

    int tz, ty, tx, d0 = 0, h0 = 0;
    bool active = true;
    if (LEV == 0) { tx = wg & 3; ty = (wg >> 2) & 7; tz = wg >> 5;
                    d0 = (sp >> 2) * 4; h0 = (sp & 3) * 8; }
    else if (LEV == 1) { tx = wg & 1; ty = (wg >> 1) & 15; tz = wg >> 5;
                    d0 = sp * 4; }
    else if (LEV == 2) { tx = 0; ty = wg & 7; tz = (wg >> 3) & 7; active = (wg < 64); }
    else { tx = 0; ty = wg & 3; tz = (wg >> 2) & 3; active = (wg < 16); }

    // hoisted tile addressing (ic-invariant)
    int goff[NL], sbyte[NL];
#pragma unroll
    for (int i = 0; i < NL; ++i) {
        int idx = i * 256 + t;
        sbyte[i] = -1;
        if (idx < TOTE) {
            int z = idx / (YT * XT), rem = idx - z * (YT * XT);
            int y = rem / XT, x = rem - y * XT;
            goff[i]  = ((d0 + z) * PS + (h0 + y)) * PS + x;
            sbyte[i] = ((z * YT + y) * XP + x) * 4;
        }
    }
    // hoisted weight addressing: 216 entries, 2 passes of 128 threads
    int wgoff[2];
    bool wok[2];
#pragma unroll
    for (int p = 0; p < 2; ++p) {
        int i = p * 128 + wg;
        wgoff[p] = 0; wok[p] = false;
        if (i < 216) {
            wgoff[p] = ((ocg * 8 + (i & 7)) * CIN) * 27 + (i >> 3);
            wok[p] = true;
        }
    }

    const uint32_t in_sa = (uint32_t)__cvta_generic_to_shared(in_s);
    const uint32_t w_sa  = (uint32_t)__cvta_generic_to_shared(w_s);

    float acc[8][8];
#pragma unroll
    for (int j = 0; j < 8; ++j)
#pragma unroll
        for (int k = 0; k < 8; ++k) acc[j][k] = 0.f;

    const float* inb = in + OFF;

    auto issue = [&](int b, int ic) {
        const float* src = inb + ic * CST;
#pragma unroll
        for (int i = 0; i < NL; ++i)
            if (sbyte[i] >= 0) cp4(in_sa + b * (TILE * 4) + sbyte[i], src + goff[i]);
#pragma unroll
        for (int p = 0; p < 2; ++p)
            if (wok[p]) cp4(w_sa + b * (216 * 4) + (p * 128 + wg) * 4,
                            wgt + ic * 27 + wgoff[p]);
    };

    issue(0, 0);
    CP_COMMIT();
    CP_WAIT0();
    __syncthreads();

    const int x0 = tx << 3;
    for (int ic = 0; ic < CIN; ++ic) {
        int cur = ic & 1, nb = cur ^ 1;
        if (ic + 1 < CIN) { issue(nb, ic + 1); CP_COMMIT(); }

        if (active) {
            const float* buf = in_s + cur * TILE;
            const float* wb  = w_s + cur * 216;
#pragma unroll
            for (int kz = 0; kz < 3; ++kz) {
#pragma unroll
                for (int ky = 0; ky < 3; ++ky) {
                    const float* ip = &buf[((tz + kz) * YT + (ty + ky)) * XP + x0];
                    float4 xa = *(const float4*)ip;
                    float4 xb = *(const float4*)(ip + 4);
                    float2 xc = *(const float2*)(ip + 8);
                    float x[10] = {xa.x, xa.y, xa.z, xa.w,
                                   xb.x, xb.y, xb.z, xb.w, xc.x, xc.y};

                    const float* wt = wb + (kz * 3 + ky) * 24;
                    float w0a[8], w1a[8], w2a[8];
                    *(float4*)&w0a[0] = *(const float4*)(wt);
                    *(float4*)&w0a[4] = *(const float4*)(wt + 4);
                    *(float4*)&w1a[0] = *(const float4*)(wt + 8);
                    *(float4*)&w1a[4] = *(const float4*)(wt + 12);
                    *(float4*)&w2a[0] = *(const float4*)(wt + 16);
                    *(float4*)&w2a[4] = *(const float4*)(wt + 20);
#pragma unroll
                    for (int j = 0; j < 8; ++j) {
                        float w0 = w0a[j], w1 = w1a[j], w2 = w2a[j];
#pragma unroll
                        for (int k = 0; k < 8; ++k) {
                            acc[j][k] = fmaf(x[k],     w0, acc[j][k]);
                            acc[j][k] = fmaf(x[k + 1], w1, acc[j][k]);
                            acc[j][k] = fmaf(x[k + 2], w2, acc[j][k]);
                        }
                    }
                }
            }
        }

        if (ic + 1 < CIN) CP_WAIT0();
        __syncthreads();
    }

    if (!active) return;
    int d = d0 + tz, h = h0 + ty;
    int pidx = ((d + 1) * PS + (h + 1)) * PS + (x0 + 1);
#pragma unroll
    for (int j = 0; j < 8; ++j) {
        int oc = ocg * 8 + j;
        float b = bias[oc];
        float* o = out + oc * CST + OFF + pidx;
#pragma unroll
        for (int k = 0; k < VV; ++k) o[k] = acc[j][k] + b;
    }
}

// ---------------------------------------------------------------------------
template <int DUMMY>
__global__ void __launch_bounds__(256, 2) conv_k8(
    const float* __restrict__ in0, const float* __restrict__ in1,
    const float* __restrict__ w0, const float* __restrict__ w1,
    const float* __restrict__ b0, const float* __restrict__ b1,
    float* __restrict__ out0, float* __restrict__ out1,
    int CIN, int g0) {

    __shared__ __align__(16) float in_s[2 * 2160];
    __shared__ __align__(16) float w_s[2 * 2 * 216];

    int gidx = blockIdx.x / 38;
    int r    = blockIdx.x - gidx * 38;
    int half = threadIdx.x >> 7;
    int head = (gidx >= g0);
    int lg   = head ? gidx - g0 : gidx;
    int ocg  = lg * 2 + half;

    const float* in   = head ? in1 : in0;
    const float* wgt  = head ? w1  : w0;
    const float* bias = head ? b1  : b0;
    float*       out  = head ? out1 : out0;
    float* wsl = w_s + half * (2 * 216);

    if (r < 32)
        conv_body8<0>(r, ocg, in, wgt, bias, out, CIN, in_s, wsl);
    else if (r < 36)
        conv_body8<1>(r - 32, ocg, in, wgt, bias, out, CIN, in_s, wsl);
    else if (r == 36)
        conv_body8<2>(0, ocg, in, wgt, bias, out, CIN, in_s, wsl);
    else
        conv_body8<3>(0, ocg, in, wgt, bias, out, CIN, in_s, wsl);
}

// ---------------------------------------------------------------------------
// VW=4 final conv body (channels-last output to d_out). 128 threads.
// ---------------------------------------------------------------------------
template <int LEV, int OCW>
__device__ __forceinline__ void conv_body4(
    int sp, int ocg,
    const float* __restrict__ in, const float* __restrict__ wgt,
    const float* __restrict__ bias, float* __restrict__ out,
    int CIN, int COUT, int head_base,
    float* __restrict__ in_s, float* __restrict__ w_s) {

    typedef Geo4<LEV> G;
    constexpr int S = G::S, PS = G::PS, OFF = G::OFF, VOX = G::VOX;
    constexpr int ZT = G::ZT, YT = G::YT, XT = G::XT, XP = G::XP;
    constexpr int TILE = ZT * YT * XP;
    constexpr int TOTE = ZT * YT * XT;
    constexpr int NL   = (TOTE + 127) / 128;

    const int t = threadIdx.x;
    int tz, ty, tx, d0 = 0, h0 = 0;
    bool active = true;
    if (LEV == 0) { tx = t & 7; ty = (t >> 3) & 7; tz = t >> 6;
                    d0 = (sp >> 2) * 2; h0 = (sp & 3) * 8; }
    else if (LEV == 1) { tx = t & 3; ty = (t >> 2) & 7; tz = t >> 5;
                    d0 = (sp >> 1) * 4; h0 = (sp & 1) * 8; }
    else if (LEV == 2) { tx = t & 1; ty = (t >> 1) & 7; tz = t >> 4; }
    else { tx = 0; ty = t & 3; tz = (t >> 2) & 3; active = (t < 16); }

    int goff[NL], sbyte[NL];
#pragma unroll
    for (int i = 0; i < NL; ++i) {
        int idx = i * 128 + t;
        sbyte[i] = -1;
        if (idx < TOTE) {
            int z = idx / (YT * XT), rem = idx - z * (YT * XT);
            int y = rem / XT, x = rem - y * XT;
            goff[i]  = ((d0 + z) * PS + (h0 + y)) * PS + x;
            sbyte[i] = ((z * YT + y) * XP + x) * 4;
        }
    }
    int wgoff[2];
    bool wok[2];
#pragma unroll
    for (int p = 0; p < 2; ++p) {
        int i = p * 128 + t;
        wgoff[p] = 0; wok[p] = false;
        if (i < 216) {
            int k = i >> 3, j = i & 7;
            int oc = ocg * OCW + j;
            if (j < OCW && oc < COUT) {
                wgoff[p] = (oc * CIN) * 27 + k;
                wok[p] = true;
            }
        }
    }

    const uint32_t in_sa = (uint32_t)__cvta_generic_to_shared(in_s);
    const uint32_t w_sa  = (uint32_t)__cvta_generic_to_shared(w_s);

    float acc[OCW][4];
#pragma unroll
    for (int j = 0; j < OCW; ++j) {
        acc[j][0] = 0.f; acc[j][1] = 0.f; acc[j][2] = 0.f; acc[j][3] = 0.f;
    }

    const float* inb = in + OFF;

    // zero the (never-loaded) padded weight slots once (j >= OCW entries)
    for (int i = t; i < 2 * 216; i += 128) w_s[i] = 0.f;
    __syncthreads();

    auto issue = [&](int b, int ic) {
        const float* src = inb + ic * CST;
#pragma unroll
        for (int i = 0; i < NL; ++i)
            if (sbyte[i] >= 0) cp4(in_sa + b * (TILE * 4) + sbyte[i], src + goff[i]);
#pragma unroll
        for (int p = 0; p < 2; ++p)
            if (wok[p]) cp4(w_sa + b * (216 * 4) + (p * 128 + t) * 4,
                            wgt + ic * 27 + wgoff[p]);
    };

    issue(0, 0);
    CP_COMMIT();
    CP_WAIT0();
    __syncthreads();

    for (int ic = 0; ic < CIN; ++ic) {
        int cur = ic & 1, nb = cur ^ 1;
        if (ic + 1 < CIN) { issue(nb, ic + 1); CP_COMMIT(); }

        if (active) {
            const float* buf = in_s + cur * TILE;
            const float* wb  = w_s + cur * 216;
#pragma unroll
            for (int kz = 0; kz < 3; ++kz) {
#pragma unroll
                for (int ky = 0; ky < 3; ++ky) {
                    const float* ip = &buf[((tz + kz) * YT + (ty + ky)) * XP + (tx << 2)];
                    float4 xa = *(const float4*)ip;
                    float2 xb = *(const float2*)(ip + 4);
                    float x0 = xa.x, x1 = xa.y, x2 = xa.z;
                    float x3 = xa.w, x4 = xb.x, x5 = xb.y;

                    const float* wt = wb + (kz * 3 + ky) * 24;
                    float w0a[8], w1a[8], w2a[8];
                    *(float4*)&w0a[0] = *(const float4*)(wt);
                    *(float4*)&w0a[4] = *(const float4*)(wt + 4);
                    *(float4*)&w1a[0] = *(const float4*)(wt + 8);
                    *(float4*)&w1a[4] = *(const float4*)(wt + 12);
                    *(float4*)&w2a[0] = *(const float4*)(wt + 16);
                    *(float4*)&w2a[4] = *(const float4*)(wt + 20);
#pragma unroll
                    for (int j = 0; j < OCW; ++j) {
                        float w0 = w0a[j], w1 = w1a[j], w2 = w2a[j];
                        acc[j][0] = fmaf(x0, w0, acc[j][0]);
                        acc[j][1] = fmaf(x1, w0, acc[j][1]);
                        acc[j][2] = fmaf(x2, w0, acc[j][2]);
                        acc[j][3] = fmaf(x3, w0, acc[j][3]);
                        acc[j][0] = fmaf(x1, w1, acc[j][0]);
                        acc[j][1] = fmaf(x2, w1, acc[j][1]);
                        acc[j][2] = fmaf(x3, w1, acc[j][2]);
                        acc[j][3] = fmaf(x4, w1, acc[j][3]);
                        acc[j][0] = fmaf(x2, w2, acc[j][0]);
                        acc[j][1] = fmaf(x3, w2, acc[j][1]);
                        acc[j][2] = fmaf(x4, w2, acc[j][2]);
                        acc[j][3] = fmaf(x5, w2, acc[j][3]);
                    }
                }
            }
        }

        if (ic + 1 < CIN) CP_WAIT0();
        __syncthreads();
    }

    if (!active) return;
    int d = d0 + tz, h = h0 + ty, w0i = tx << 2;
    int vidx = (d * S + h) * S + w0i;
#pragma unroll
    for (int j = 0; j < OCW; ++j) {
        int oc = ocg * OCW + j;
        if (oc >= COUT) break;
        float b = bias[oc];
        int base = head_base + (VOX + vidx) * COUT + oc;
        out[base + 0 * COUT] = acc[j][0] + b;
        out[base + 1 * COUT] = acc[j][1] + b;
        out[base + 2 * COUT] = acc[j][2] + b;
        out[base + 3 * COUT] = acc[j][3] + b;
    }
}

// ---------------------------------------------------------------------------
template <int OCW>
__global__ void __launch_bounds__(128) conv_kf(
    const float* __restrict__ in0, const float* __restrict__ in1,
    const float* __restrict__ w0, const float* __restrict__ w1,
    const float* __restrict__ b0, const float* __restrict__ b1,
    float* __restrict__ out,
    int CIN, int COUT0, int COUT1, int g0, int base1) {

    __shared__ __align__(16) float in_s[2 * 1440];
    __shared__ __align__(16) float w_s[2 * 216];

    int gidx = blockIdx.x / 74;
    int r    = blockIdx.x - gidx * 74;
    int head = (gidx >= g0);
    int ocg  = head ? gidx - g0 : gidx;

    const float* in   = head ? in1 : in0;
    const float* wgt  = head ? w1  : w0;
    const float* bias = head ? b1  : b0;
    int COUT  = head ? COUT1 : COUT0;
    int hbase = head ? base1 : 0;

    if (r < 64)
        conv_body4<0, OCW>(r, ocg, in, wgt, bias, out, CIN, COUT, hbase, in_s, w_s);
    else if (r < 72)
        conv_body4<1, OCW>(r - 64, ocg, in, wgt, bias, out, CIN, COUT, hbase, in_s, w_s);
    else if (r == 72)
        conv_body4<2, OCW>(0, ocg, in, wgt, bias, out, CIN, COUT, hbase, in_s, w_s);
    else
        conv_body4<3, OCW>(0, ocg, in, wgt, bias, out, CIN, COUT, hbase, in_s, w_s);
}

// ---------------------------------------------------------------------------
extern "C" void kernel_launch(void* const* d_in, const int* in_sizes, int n_in,
                              void* d_out, int out_size) {
    (void)in_sizes; (void)n_in; (void)out_size;

    const float* p0 = (const float*)d_in[0];
    const float* p1 = (const float*)d_in[1];
    const float* p2 = (const float*)d_in[2];
    const float* p3 = (const float*)d_in[3];

    const float* cw1   = (const float*)d_in[4];
    const float* cb1   = (const float*)d_in[5];
    const float* cw234 = (const float*)d_in[6];
    const float* cb234 = (const float*)d_in[7];
    const float* ca    = (const float*)d_in[8];
    const float* cwf   = (const float*)d_in[9];
    const float* cbf   = (const float*)d_in[10];
    const float* rw1   = (const float*)d_in[11];
    const float* rb1   = (const float*)d_in[12];
    const float* rw234 = (const float*)d_in[13];
    const float* rb234 = (const float*)d_in[14];
    const float* ra    = (const float*)d_in[15];
    const float* rwf   = (const float*)d_in[16];
    const float* rbf   = (const float*)d_in[17];

    float *in36, *buf, *mean, *rstd;
    cudaGetSymbolAddress((void**)&in36, g_in36);
    cudaGetSymbolAddress((void**)&buf,  g_buf);
    cudaGetSymbolAddress((void**)&mean, g_mean);
    cudaGetSymbolAddress((void**)&rstd, g_rstd);

    float* A0 = buf;
    float* B0 = buf + (size_t)64 * CST;
    float* A1 = buf + (size_t)2 * 64 * CST;
    float* B1 = buf + (size_t)3 * 64 * CST;
    float* out = (float*)d_out;
    const int CLS_TOTAL = 37440 * 18;

    pack_kernel<<<dim3(147, 36), 256>>>(p0, p1, p2, p3, in36);

    // conv1 (36->64, raw input), both heads: 8 grid-groups x 38 tiles
    conv_k8<0><<<8 * 38, 256>>>(in36, in36, cw1, rw1, cb1, rb1, A0, A1, 36, 4);
    stats2_kernel<<<512, 256>>>(A0, A1, mean, rstd);
    np_kernel<<<dim3(147, 64, 2), 256>>>(A0, A1, mean, rstd, ca, ra, 0);

    float* s0 = A0; float* d0p = B0;
    float* s1 = A1; float* d1p = B1;
    for (int i = 0; i < 3; ++i) {
        conv_k8<0><<<8 * 38, 256>>>(
            s0, s1, cw234 + (size_t)i * 64 * 64 * 27, rw234 + (size_t)i * 64 * 64 * 27,
            cb234 + i * 64, rb234 + i * 64, d0p, d1p, 64, 4);
        stats2_kernel<<<512, 256>>>(d0p, d1p, mean, rstd);
        np_kernel<<<dim3(147, 64, 2), 256>>>(d0p, d1p, mean, rstd, ca, ra, i + 1);
        float* t0 = s0; s0 = d0p; d0p = t0;
        float* t1 = s1; s1 = d1p; d1p = t1;
    }

    // final conv: cls COUT=18 (3 oc-groups of 6), reg COUT=54 (9 groups of 6)
    conv_kf<6><<<12 * 74, 128>>>(
        s0, s1, cwf, rwf, cbf, rbf, out, 64, 18, 54, 3, CLS_TOTAL);
}

// round 10
// speedup vs baseline: 2.1895x; 1.0184x over previous
#include <cuda_runtime.h>
#include <cstdint>

// ---------------------------------------------------------------------------
// Padded layout: per level, channel-plane is (S+2)^3 with 1-voxel zero halo.
// Halos are never written -> stay zero (zero-initialized __device__ globals).
// ---------------------------------------------------------------------------
#define CST 46352   // padded channel stride = 34^3 + 18^3 + 10^3 + 6^3

__device__ float g_in36[36 * CST];
__device__ float g_buf[2][2][64 * CST];   // [head][pingpong]
__device__ float g_mean[512];             // [head][L][c]
__device__ float g_rstd[512];
__device__ float g_part[2 * 64 * 38 * 2]; // [head][oc][tile][s,q]

__device__ __forceinline__ void cp4(uint32_t d, const float* s) {
    asm volatile("cp.async.ca.shared.global [%0], [%1], 4;" :: "r"(d), "l"(s));
}
#define CP_COMMIT() asm volatile("cp.async.commit_group;" ::: "memory")
#define CP_WAIT0()  asm volatile("cp.async.wait_group 0;" ::: "memory")

// ---------------------------------------------------------------------------
// Pack inputs into padded layout (interior only; halos stay zero).
// ---------------------------------------------------------------------------
__global__ void pack_kernel(const float* __restrict__ p0, const float* __restrict__ p1,
                            const float* __restrict__ p2, const float* __restrict__ p3,
                            float* __restrict__ out) {
    int c = blockIdx.y;
    int pos = blockIdx.x * 256 + threadIdx.x;
    if (pos >= 37440) return;
    const float* p; int v, S, PS, OF, lg;
    if (pos < 32768)      { p = p0; v = pos;         S = 32; PS = 34; OF = 0;     lg = 5; }
    else if (pos < 36864) { p = p1; v = pos - 32768; S = 16; PS = 18; OF = 39304; lg = 4; }
    else if (pos < 37376) { p = p2; v = pos - 36864; S = 8;  PS = 10; OF = 45136; lg = 3; }
    else                  { p = p3; v = pos - 37376; S = 4;  PS = 6;  OF = 46136; lg = 2; }
    int w = v & (S - 1), h = (v >> lg) & (S - 1), d = v >> (2 * lg);
    out[c * CST + OF + ((d + 1) * PS + h + 1) * PS + (w + 1)] =
        p[c * (S * S * S) + v];
}

// ---------------------------------------------------------------------------
// Reduce per-tile conv partials into mean/rstd. Block per (head,L,c).
// Tile slots: L0 r=0..31, L1 r=32..35, L2 r=36, L3 r=37. Deterministic.
// ---------------------------------------------------------------------------
__global__ void reduce_kernel(float* __restrict__ mean, float* __restrict__ rstd) {
    int head = blockIdx.x >> 8, sub = blockIdx.x & 255;
    int L = sub >> 6, c = sub & 63;
    const int basev[4] = {0, 32, 36, 37}, cntv[4] = {32, 4, 1, 1};
    const float invN[4] = {1.f / 32768.f, 1.f / 4096.f, 1.f / 512.f, 1.f / 64.f};
    int t = threadIdx.x;
    float s = 0.f, q = 0.f;
    if (t < cntv[L]) {
        int idx = (((head << 6) + c) * 38 + basev[L] + t) * 2;
        s = g_part[idx];
        q = g_part[idx + 1];
    }
#pragma unroll
    for (int o = 16; o > 0; o >>= 1) {
        s += __shfl_down_sync(0xffffffffu, s, o);
        q += __shfl_down_sync(0xffffffffu, q, o);
    }
    if (t == 0) {
        float m = s * invN[L];
        float v = q * invN[L] - m * m;
        mean[blockIdx.x] = m;
        rstd[blockIdx.x] = rsqrtf(fmaxf(v, 0.f) + 1e-5f);
    }
}

// ---------------------------------------------------------------------------
// In-place InstanceNorm + PReLU, fully voxel-parallel (one elem per thread).
// grid = (147, 64 channels, 2 heads).
// ---------------------------------------------------------------------------
__global__ void np_kernel(float* __restrict__ b0, float* __restrict__ b1,
                          const float* __restrict__ mean, const float* __restrict__ rstd,
                          const float* __restrict__ a0, const float* __restrict__ a1,
                          int aidx) {
    int c = blockIdx.y, head = blockIdx.z;
    int pos = blockIdx.x * 256 + threadIdx.x;
    if (pos >= 37440) return;
    int v, S, PS, OF, lg, L;
    if (pos < 32768)      { v = pos;         S = 32; PS = 34; OF = 0;     lg = 5; L = 0; }
    else if (pos < 36864) { v = pos - 32768; S = 16; PS = 18; OF = 39304; lg = 4; L = 1; }
    else if (pos < 37376) { v = pos - 36864; S = 8;  PS = 10; OF = 45136; lg = 3; L = 2; }
    else                  { v = pos - 37376; S = 4;  PS = 6;  OF = 46136; lg = 2; L = 3; }
    int w = v & (S - 1), h = (v >> lg) & (S - 1), d = v >> (2 * lg);
    float* p = (head ? b1 : b0) + c * CST + OF + ((d + 1) * PS + h + 1) * PS + (w + 1);
    int si = head * 256 + L * 64 + c;
    float m = __ldg(mean + si), r = __ldg(rstd + si);
    float alpha = __ldg((head ? a1 : a0) + aidx);
    float x = (*p - m) * r;
    *p = x >= 0.f ? x : alpha * x;
}

// ---------------------------------------------------------------------------
// Geometry. XT = full padded width (S+2); XP padded to mult of 4 for LDS.128.
template <int LEV> struct Geo8;
template <> struct Geo8<0> { enum { S = 32, PS = 34, OFF = 0,     ZT = 6,  YT = 10, XT = 34, XP = 36 }; };
template <> struct Geo8<1> { enum { S = 16, PS = 18, OFF = 39304, ZT = 6,  YT = 18, XT = 18, XP = 20 }; };
template <> struct Geo8<2> { enum { S = 8,  PS = 10, OFF = 45136, ZT = 10, YT = 10, XT = 10, XP = 12 }; };
template <> struct Geo8<3> { enum { S = 4,  PS = 6,  OFF = 46136, ZT = 6,  YT = 6,  XT = 6,  XP = 12 }; };

template <int LEV> struct Geo4;
template <> struct Geo4<0> { enum { S = 32, PS = 34, OFF = 0,     VOX = 0,     ZT = 4,  YT = 10, XT = 34, XP = 36 }; };
template <> struct Geo4<1> { enum { S = 16, PS = 18, OFF = 39304, VOX = 32768, ZT = 6,  YT = 10, XT = 18, XP = 20 }; };
template <> struct Geo4<2> { enum { S = 8,  PS = 10, OFF = 45136, VOX = 36864, ZT = 10, YT = 10, XT = 10, XP = 12 }; };
template <> struct Geo4<3> { enum { S = 4,  PS = 6,  OFF = 46136, VOX = 37376, ZT = 6,  YT = 6,  XT = 6,  XP = 8  }; };

// ---------------------------------------------------------------------------
// VW=8 conv body. 256 threads = 2 halves x 8 oc. cp.async staging, padded
// layout (no bounds checks), double-buffered, one barrier per ic.
// Epilogue: per-(block-half, oc) partial sums (s, q) -> g_part[head][oc][r].
// ---------------------------------------------------------------------------
template <int LEV>
__device__ __forceinline__ void conv_body8(
    int sp, int ocg, int head, int r,
    const float* __restrict__ in, const float* __restrict__ wgt,
    const float* __restrict__ bias, float* __restrict__ out,
    int CIN, float* __restrict__ in_s, float* __restrict__ w_s) {

    typedef Geo8<LEV> G;
    constexpr int PS = G::PS, OFF = G::OFF;
    constexpr int ZT = G::ZT, YT = G::YT, XT = G::XT, XP = G::XP;
    constexpr int TILE = ZT * YT * XP;
    constexpr int TOTE = ZT * YT * XT;
    constexpr int NL   = (TOTE + 255) / 256;
    constexpr int VV   = (LEV == 3) ? 4 : 8;

    const int t  = threadIdx.x;
    const int wg = t & 127;

    int tz, ty, tx, d0 = 0, h0 = 0;
    bool active = true;
    if (LEV == 0) { tx = wg & 3; ty = (wg >> 2) & 7; tz = wg >> 5;
                    d0 = (sp >> 2) * 4; h0 = (sp & 3) * 8; }
    else if (LEV == 1) { tx = wg & 1; ty = (wg >> 1) & 15; tz = wg >> 5;
                    d0 = sp * 4; }
    else if (LEV == 2) { tx = 0; ty = wg & 7; tz = (wg >> 3) & 7; active = (wg < 64); }
    else { tx = 0; ty = wg & 3; tz = (wg >> 2) & 3; active = (wg < 16); }

    // hoisted tile addressing (ic-invariant)
    int goff[NL], sbyte[NL];
#pragma unroll
    for (int i = 0; i < NL; ++i) {
        int idx = i * 256 + t;
        sbyte[i] = -1;
        if (idx < TOTE) {
            int z = idx / (YT * XT), rem = idx - z * (YT * XT);
            int y = rem / XT, x = rem - y * XT;
            goff[i]  = ((d0 + z) * PS + (h0 + y)) * PS + x;
            sbyte[i] = ((z * YT + y) * XP + x) * 4;
        }
    }
    // hoisted weight addressing: 216 entries, 2 passes of 128 threads
    int wgoff[2];
    bool wok[2];
#pragma unroll
    for (int p = 0; p < 2; ++p) {
        int i = p * 128 + wg;
        wgoff[p] = 0; wok[p] = false;
        if (i < 216) {
            wgoff[p] = ((ocg * 8 + (i & 7)) * CIN) * 27 + (i >> 3);
            wok[p] = true;
        }
    }

    const uint32_t in_sa = (uint32_t)__cvta_generic_to_shared(in_s);
    const uint32_t w_sa  = (uint32_t)__cvta_generic_to_shared(w_s);

    float acc[8][8];
#pragma unroll
    for (int j = 0; j < 8; ++j)
#pragma unroll
        for (int k = 0; k < 8; ++k) acc[j][k] = 0.f;

    const float* inb = in + OFF;

    auto issue = [&](int b, int ic) {
        const float* src = inb + ic * CST;
#pragma unroll
        for (int i = 0; i < NL; ++i)
            if (sbyte[i] >= 0) cp4(in_sa + b * (TILE * 4) + sbyte[i], src + goff[i]);
#pragma unroll
        for (int p = 0; p < 2; ++p)
            if (wok[p]) cp4(w_sa + b * (216 * 4) + (p * 128 + wg) * 4,
                            wgt + ic * 27 + wgoff[p]);
    };

    issue(0, 0);
    CP_COMMIT();
    CP_WAIT0();
    __syncthreads();

    const int x0 = tx << 3;
    for (int ic = 0; ic < CIN; ++ic) {
        int cur = ic & 1, nb = cur ^ 1;
        if (ic + 1 < CIN) { issue(nb, ic + 1); CP_COMMIT(); }

        if (active) {
            const float* buf = in_s + cur * TILE;
            const float* wb  = w_s + cur * 216;
#pragma unroll
            for (int kz = 0; kz < 3; ++kz) {
#pragma unroll
                for (int ky = 0; ky < 3; ++ky) {
                    const float* ip = &buf[((tz + kz) * YT + (ty + ky)) * XP + x0];
                    float4 xa = *(const float4*)ip;
                    float4 xb = *(const float4*)(ip + 4);
                    float2 xc = *(const float2*)(ip + 8);
                    float x[10] = {xa.x, xa.y, xa.z, xa.w,
                                   xb.x, xb.y, xb.z, xb.w, xc.x, xc.y};

                    const float* wt = wb + (kz * 3 + ky) * 24;
                    float w0a[8], w1a[8], w2a[8];
                    *(float4*)&w0a[0] = *(const float4*)(wt);
                    *(float4*)&w0a[4] = *(const float4*)(wt + 4);
                    *(float4*)&w1a[0] = *(const float4*)(wt + 8);
                    *(float4*)&w1a[4] = *(const float4*)(wt + 12);
                    *(float4*)&w2a[0] = *(const float4*)(wt + 16);
                    *(float4*)&w2a[4] = *(const float4*)(wt + 20);
#pragma unroll
                    for (int j = 0; j < 8; ++j) {
                        float w0 = w0a[j], w1 = w1a[j], w2 = w2a[j];
#pragma unroll
                        for (int k = 0; k < 8; ++k) {
                            acc[j][k] = fmaf(x[k],     w0, acc[j][k]);
                            acc[j][k] = fmaf(x[k + 1], w1, acc[j][k]);
                            acc[j][k] = fmaf(x[k + 2], w2, acc[j][k]);
                        }
                    }
                }
            }
        }

        if (ic + 1 < CIN) CP_WAIT0();
        __syncthreads();
    }

    // ---- output store + biased values for stats (active threads only) ----
    float s8[8], q8[8];
#pragma unroll
    for (int j = 0; j < 8; ++j) { s8[j] = 0.f; q8[j] = 0.f; }

    if (active) {
        int d = d0 + tz, h = h0 + ty;
        int pidx = ((d + 1) * PS + (h + 1)) * PS + (x0 + 1);
#pragma unroll
        for (int j = 0; j < 8; ++j) {
            int oc = ocg * 8 + j;
            float b = bias[oc];
            float* o = out + oc * CST + OFF + pidx;
#pragma unroll
            for (int k = 0; k < VV; ++k) {
                float ov = acc[j][k] + b;
                o[k] = ov;
                s8[j] += ov;
                q8[j] = fmaf(ov, ov, q8[j]);
            }
        }
    }

    // ---- stats epilogue: reduce (s,q) per oc over the 128-thread half ----
#pragma unroll
    for (int j = 0; j < 8; ++j) {
#pragma unroll
        for (int o = 16; o > 0; o >>= 1) {
            s8[j] += __shfl_down_sync(0xffffffffu, s8[j], o);
            q8[j] += __shfl_down_sync(0xffffffffu, q8[j], o);
        }
    }
    int warp = wg >> 5, lane = t & 31;
    if (lane == 0) {
#pragma unroll
        for (int j = 0; j < 8; ++j) {
            w_s[warp * 16 + j * 2]     = s8[j];
            w_s[warp * 16 + j * 2 + 1] = q8[j];
        }
    }
    __syncthreads();
    if (wg < 8) {
        int j = wg;
        float s = 0.f, q = 0.f;
#pragma unroll
        for (int w2 = 0; w2 < 4; ++w2) {
            s += w_s[w2 * 16 + j * 2];
            q += w_s[w2 * 16 + j * 2 + 1];
        }
        int oc = ocg * 8 + j;
        int idx = (((head << 6) + oc) * 38 + r) * 2;
        g_part[idx]     = s;
        g_part[idx + 1] = q;
    }
}

// ---------------------------------------------------------------------------
template <int DUMMY>
__global__ void __launch_bounds__(256, 2) conv_k8(
    const float* __restrict__ in0, const float* __restrict__ in1,
    const float* __restrict__ w0, const float* __restrict__ w1,
    const float* __restrict__ b0, const float* __restrict__ b1,
    float* __restrict__ out0, float* __restrict__ out1,
    int CIN, int g0) {

    __shared__ __align__(16) float in_s[2 * 2160];
    __shared__ __align__(16) float w_s[2 * 2 * 216];

    int gidx = blockIdx.x / 38;
    int r    = blockIdx.x - gidx * 38;
    int half = threadIdx.x >> 7;
    int head = (gidx >= g0);
    int lg   = head ? gidx - g0 : gidx;
    int ocg  = lg * 2 + half;

    const float* in   = head ? in1 : in0;
    const float* wgt  = head ? w1  : w0;
    const float* bias = head ? b1  : b0;
    float*       out  = head ? out1 : out0;
    float* wsl = w_s + half * (2 * 216);

    if (r < 32)
        conv_body8<0>(r, ocg, head, r, in, wgt, bias, out, CIN, in_s, wsl);
    else if (r < 36)
        conv_body8<1>(r - 32, ocg, head, r, in, wgt, bias, out, CIN, in_s, wsl);
    else if (r == 36)
        conv_body8<2>(0, ocg, head, r, in, wgt, bias, out, CIN, in_s, wsl);
    else
        conv_body8<3>(0, ocg, head, r, in, wgt, bias, out, CIN, in_s, wsl);
}

// ---------------------------------------------------------------------------
// VW=4 final conv body (channels-last output to d_out). 128 threads.
// ---------------------------------------------------------------------------
template <int LEV, int OCW>
__device__ __forceinline__ void conv_body4(
    int sp, int ocg,
    const float* __restrict__ in, const float* __restrict__ wgt,
    const float* __restrict__ bias, float* __restrict__ out,
    int CIN, int COUT, int head_base,
    float* __restrict__ in_s, float* __restrict__ w_s) {

    typedef Geo4<LEV> G;
    constexpr int S = G::S, PS = G::PS, OFF = G::OFF, VOX = G::VOX;
    constexpr int ZT = G::ZT, YT = G::YT, XT = G::XT, XP = G::XP;
    constexpr int TILE = ZT * YT * XP;
    constexpr int TOTE = ZT * YT * XT;
    constexpr int NL   = (TOTE + 127) / 128;

    const int t = threadIdx.x;
    int tz, ty, tx, d0 = 0, h0 = 0;
    bool active = true;
    if (LEV == 0) { tx = t & 7; ty = (t >> 3) & 7; tz = t >> 6;
                    d0 = (sp >> 2) * 2; h0 = (sp & 3) * 8; }
    else if (LEV == 1) { tx = t & 3; ty = (t >> 2) & 7; tz = t >> 5;
                    d0 = (sp >> 1) * 4; h0 = (sp & 1) * 8; }
    else if (LEV == 2) { tx = t & 1; ty = (t >> 1) & 7; tz = t >> 4; }
    else { tx = 0; ty = t & 3; tz = (t >> 2) & 3; active = (t < 16); }

    int goff[NL], sbyte[NL];
#pragma unroll
    for (int i = 0; i < NL; ++i) {
        int idx = i * 128 + t;
        sbyte[i] = -1;
        if (idx < TOTE) {
            int z = idx / (YT * XT), rem = idx - z * (YT * XT);
            int y = rem / XT, x = rem - y * XT;
            goff[i]  = ((d0 + z) * PS + (h0 + y)) * PS + x;
            sbyte[i] = ((z * YT + y) * XP + x) * 4;
        }
    }
    int wgoff[2];
    bool wok[2];
#pragma unroll
    for (int p = 0; p < 2; ++p) {
        int i = p * 128 + t;
        wgoff[p] = 0; wok[p] = false;
        if (i < 216) {
            int k = i >> 3, j = i & 7;
            int oc = ocg * OCW + j;
            if (j < OCW && oc < COUT) {
                wgoff[p] = (oc * CIN) * 27 + k;
                wok[p] = true;
            }
        }
    }

    const uint32_t in_sa = (uint32_t)__cvta_generic_to_shared(in_s);
    const uint32_t w_sa  = (uint32_t)__cvta_generic_to_shared(w_s);

    float acc[OCW][4];
#pragma unroll
    for (int j = 0; j < OCW; ++j) {
        acc[j][0] = 0.f; acc[j][1] = 0.f; acc[j][2] = 0.f; acc[j][3] = 0.f;
    }

    const float* inb = in + OFF;

    // zero the (never-loaded) padded weight slots once (j >= OCW entries)
    for (int i = t; i < 2 * 216; i += 128) w_s[i] = 0.f;
    __syncthreads();

    auto issue = [&](int b, int ic) {
        const float* src = inb + ic * CST;
#pragma unroll
        for (int i = 0; i < NL; ++i)
            if (sbyte[i] >= 0) cp4(in_sa + b * (TILE * 4) + sbyte[i], src + goff[i]);
#pragma unroll
        for (int p = 0; p < 2; ++p)
            if (wok[p]) cp4(w_sa + b * (216 * 4) + (p * 128 + t) * 4,
                            wgt + ic * 27 + wgoff[p]);
    };

    issue(0, 0);
    CP_COMMIT();
    CP_WAIT0();
    __syncthreads();

    for (int ic = 0; ic < CIN; ++ic) {
        int cur = ic & 1, nb = cur ^ 1;
        if (ic + 1 < CIN) { issue(nb, ic + 1); CP_COMMIT(); }

        if (active) {
            const float* buf = in_s + cur * TILE;
            const float* wb  = w_s + cur * 216;
#pragma unroll
            for (int kz = 0; kz < 3; ++kz) {
#pragma unroll
                for (int ky = 0; ky < 3; ++ky) {
                    const float* ip = &buf[((tz + kz) * YT + (ty + ky)) * XP + (tx << 2)];
                    float4 xa = *(const float4*)ip;
                    float2 xb = *(const float2*)(ip + 4);
                    float x0 = xa.x, x1 = xa.y, x2 = xa.z;
                    float x3 = xa.w, x4 = xb.x, x5 = xb.y;

                    const float* wt = wb + (kz * 3 + ky) * 24;
                    float w0a[8], w1a[8], w2a[8];
                    *(float4*)&w0a[0] = *(const float4*)(wt);
                    *(float4*)&w0a[4] = *(const float4*)(wt + 4);
                    *(float4*)&w1a[0] = *(const float4*)(wt + 8);
                    *(float4*)&w1a[4] = *(const float4*)(wt + 12);
                    *(float4*)&w2a[0] = *(const float4*)(wt + 16);
                    *(float4*)&w2a[4] = *(const float4*)(wt + 20);
#pragma unroll
                    for (int j = 0; j < OCW; ++j) {
                        float w0 = w0a[j], w1 = w1a[j], w2 = w2a[j];
                        acc[j][0] = fmaf(x0, w0, acc[j][0]);
                        acc[j][1] = fmaf(x1, w0, acc[j][1]);
                        acc[j][2] = fmaf(x2, w0, acc[j][2]);
                        acc[j][3] = fmaf(x3, w0, acc[j][3]);
                        acc[j][0] = fmaf(x1, w1, acc[j][0]);
                        acc[j][1] = fmaf(x2, w1, acc[j][1]);
                        acc[j][2] = fmaf(x3, w1, acc[j][2]);
                        acc[j][3] = fmaf(x4, w1, acc[j][3]);
                        acc[j][0] = fmaf(x2, w2, acc[j][0]);
                        acc[j][1] = fmaf(x3, w2, acc[j][1]);
                        acc[j][2] = fmaf(x4, w2, acc[j][2]);
                        acc[j][3] = fmaf(x5, w2, acc[j][3]);
                    }
                }
            }
        }

        if (ic + 1 < CIN) CP_WAIT0();
        __syncthreads();
    }

    if (!active) return;
    int d = d0 + tz, h = h0 + ty, w0i = tx << 2;
    int vidx = (d * S + h) * S + w0i;
#pragma unroll
    for (int j = 0; j < OCW; ++j) {
        int oc = ocg * OCW + j;
        if (oc >= COUT) break;
        float b = bias[oc];
        int base = head_base + (VOX + vidx) * COUT + oc;
        out[base + 0 * COUT] = acc[j][0] + b;
        out[base + 1 * COUT] = acc[j][1] + b;
        out[base + 2 * COUT] = acc[j][2] + b;
        out[base + 3 * COUT] = acc[j][3] + b;
    }
}

// ---------------------------------------------------------------------------
template <int OCW>
__global__ void __launch_bounds__(128) conv_kf(
    const float* __restrict__ in0, const float* __restrict__ in1,
    const float* __restrict__ w0, const float* __restrict__ w1,
    const float* __restrict__ b0, const float* __restrict__ b1,
    float* __restrict__ out,
    int CIN, int COUT0, int COUT1, int g0, int base1) {

    __shared__ __align__(16) float in_s[2 * 1440];
    __shared__ __align__(16) float w_s[2 * 216];

    int gidx = blockIdx.x / 74;
    int r    = blockIdx.x - gidx * 74;
    int head = (gidx >= g0);
    int ocg  = head ? gidx - g0 : gidx;

    const float* in   = head ? in1 : in0;
    const float* wgt  = head ? w1  : w0;
    const float* bias = head ? b1  : b0;
    int COUT  = head ? COUT1 : COUT0;
    int hbase = head ? base1 : 0;

    if (r < 64)
        conv_body4<0, OCW>(r, ocg, in, wgt, bias, out, CIN, COUT, hbase, in_s, w_s);
    else if (r < 72)
        conv_body4<1, OCW>(r - 64, ocg, in, wgt, bias, out, CIN, COUT, hbase, in_s, w_s);
    else if (r == 72)
        conv_body4<2, OCW>(0, ocg, in, wgt, bias, out, CIN, COUT, hbase, in_s, w_s);
    else
        conv_body4<3, OCW>(0, ocg, in, wgt, bias, out, CIN, COUT, hbase, in_s, w_s);
}

// ---------------------------------------------------------------------------
extern "C" void kernel_launch(void* const* d_in, const int* in_sizes, int n_in,
                              void* d_out, int out_size) {
    (void)in_sizes; (void)n_in; (void)out_size;

    const float* p0 = (const float*)d_in[0];
    const float* p1 = (const float*)d_in[1];
    const float* p2 = (const float*)d_in[2];
    const float* p3 = (const float*)d_in[3];

    const float* cw1   = (const float*)d_in[4];
    const float* cb1   = (const float*)d_in[5];
    const float* cw234 = (const float*)d_in[6];
    const float* cb234 = (const float*)d_in[7];
    const float* ca    = (const float*)d_in[8];
    const float* cwf   = (const float*)d_in[9];
    const float* cbf   = (const float*)d_in[10];
    const float* rw1   = (const float*)d_in[11];
    const float* rb1   = (const float*)d_in[12];
    const float* rw234 = (const float*)d_in[13];
    const float* rb234 = (const float*)d_in[14];
    const float* ra    = (const float*)d_in[15];
    const float* rwf   = (const float*)d_in[16];
    const float* rbf   = (const float*)d_in[17];

    float *in36, *buf, *mean, *rstd;
    cudaGetSymbolAddress((void**)&in36, g_in36);
    cudaGetSymbolAddress((void**)&buf,  g_buf);
    cudaGetSymbolAddress((void**)&mean, g_mean);
    cudaGetSymbolAddress((void**)&rstd, g_rstd);

    float* A0 = buf;
    float* B0 = buf + (size_t)64 * CST;
    float* A1 = buf + (size_t)2 * 64 * CST;
    float* B1 = buf + (size_t)3 * 64 * CST;
    float* out = (float*)d_out;
    const int CLS_TOTAL = 37440 * 18;

    pack_kernel<<<dim3(147, 36), 256>>>(p0, p1, p2, p3, in36);

    // conv1 (36->64, raw input), both heads; epilogue writes stats partials
    conv_k8<0><<<8 * 38, 256>>>(in36, in36, cw1, rw1, cb1, rb1, A0, A1, 36, 4);
    reduce_kernel<<<512, 32>>>(mean, rstd);
    np_kernel<<<dim3(147, 64, 2), 256>>>(A0, A1, mean, rstd, ca, ra, 0);

    float* s0 = A0; float* d0p = B0;
    float* s1 = A1; float* d1p = B1;
    for (int i = 0; i < 3; ++i) {
        conv_k8<0><<<8 * 38, 256>>>(
            s0, s1, cw234 + (size_t)i * 64 * 64 * 27, rw234 + (size_t)i * 64 * 64 * 27,
            cb234 + i * 64, rb234 + i * 64, d0p, d1p, 64, 4);
        reduce_kernel<<<512, 32>>>(mean, rstd);
        np_kernel<<<dim3(147, 64, 2), 256>>>(d0p, d1p, mean, rstd, ca, ra, i + 1);
        float* t0 = s0; s0 = d0p; d0p = t0;
        float* t1 = s1; s1 = d1p; d1p = t1;
    }

    // final conv: cls COUT=18 (3 oc-groups of 6), reg COUT=54 (9 groups of 6)
    conv_kf<6><<<12 * 74, 128>>>(
        s0, s1, cwf, rwf, cbf, rbf, out, 64, 18, 54, 3, CLS_TOTAL);
}